// round 2
// baseline (speedup 1.0000x reference)
#include <cuda_runtime.h>
#include <stdint.h>

// GCNConvDGL: out = segment_sum(x[src] -> dst) @ W + bias
// x: [50000, 512] f32, W: [512, 512] f32, bias: [512] f32,
// src/dst: [800000] int32 (JAX x64-disabled downcasts int64 -> int32),
// out: [50000, 512] f32

#define N_NODES 50000
#define N_EDGES 800000
#define D       512

// Scratch: aggregated features (fp32). ~102.4 MB static device array.
__device__ float g_agg[(size_t)N_NODES * D];

// ---------------------------------------------------------------------------
// Phase 1: zero the aggregation buffer (float4 stores)
// ---------------------------------------------------------------------------
__global__ void zero_kernel(size_t n4) {
    size_t i = (size_t)blockIdx.x * blockDim.x + threadIdx.x;
    if (i < n4) {
        ((float4*)g_agg)[i] = make_float4(0.f, 0.f, 0.f, 0.f);
    }
}

// ---------------------------------------------------------------------------
// Phase 2: scatter-add. One warp per edge; each lane handles 4 float4 chunks
// of the 512-float row. red.global.add.v4.f32 = no-return vectorized reduce.
// ---------------------------------------------------------------------------
__global__ void __launch_bounds__(256) scatter_kernel(
    const float* __restrict__ x,
    const int* __restrict__ src,
    const int* __restrict__ dst)
{
    int warp = (int)((blockIdx.x * (size_t)blockDim.x + threadIdx.x) >> 5);
    int lane = threadIdx.x & 31;
    if (warp >= N_EDGES) return;

    int s = src[warp];
    int d = dst[warp];
    const float4* xr = (const float4*)(x + (size_t)s * D);
    float* ar = g_agg + (size_t)d * D;

    #pragma unroll
    for (int i = 0; i < 4; i++) {
        int c4 = lane + i * 32;            // float4 index within row: 0..127
        float4 v = xr[c4];
        asm volatile(
            "red.global.add.v4.f32 [%0], {%1, %2, %3, %4};"
            :: "l"(ar + c4 * 4), "f"(v.x), "f"(v.y), "f"(v.z), "f"(v.w)
            : "memory");
    }
}

// ---------------------------------------------------------------------------
// Phase 3: fp32 SIMT GEMM  C[M,512] = A[M,512] @ B[512,512] + bias
// 128x128 block tile, BK=8, 256 threads, 8x8 per-thread register tile.
// ---------------------------------------------------------------------------
#define BM 128
#define BN 128
#define BK 8
#define TM 8
#define TN 8

__global__ void __launch_bounds__(256) gemm_kernel(
    const float* __restrict__ A,     // g_agg [M, 512]
    const float* __restrict__ B,     // weight [512, 512]
    const float* __restrict__ bias,  // [512]
    float* __restrict__ C,           // out [M, 512]
    int M)
{
    __shared__ float As[BK][BM];
    __shared__ float Bs[BK][BN];

    const int tid = threadIdx.x;
    const int block_m = blockIdx.y * BM;
    const int block_n = blockIdx.x * BN;

    // A tile load mapping: 128 rows x 8 cols = 1024 floats = 256 float4
    const int a_row  = tid >> 1;          // 0..127
    const int a_col4 = (tid & 1) * 4;     // 0 or 4
    // B tile load mapping: 8 rows x 128 cols = 256 float4
    const int b_row = tid >> 5;           // 0..7
    const int b_col = (tid & 31) * 4;     // 0..124

    // Compute mapping: 16x16 threads, each 8x8 outputs
    const int tm = (tid >> 4) * TM;
    const int tn = (tid & 15) * TN;

    float acc[TM][TN];
    #pragma unroll
    for (int i = 0; i < TM; i++)
        #pragma unroll
        for (int j = 0; j < TN; j++)
            acc[i][j] = 0.f;

    for (int k0 = 0; k0 < D; k0 += BK) {
        // Load A tile (transposed into As[k][m]), guard M boundary
        int gr = block_m + a_row;
        float4 av = make_float4(0.f, 0.f, 0.f, 0.f);
        if (gr < M)
            av = *(const float4*)(A + (size_t)gr * D + k0 + a_col4);
        As[a_col4 + 0][a_row] = av.x;
        As[a_col4 + 1][a_row] = av.y;
        As[a_col4 + 2][a_row] = av.z;
        As[a_col4 + 3][a_row] = av.w;

        // Load B tile
        float4 bv = *(const float4*)(B + (size_t)(k0 + b_row) * D + block_n + b_col);
        *(float4*)&Bs[b_row][b_col] = bv;

        __syncthreads();

        #pragma unroll
        for (int k = 0; k < BK; k++) {
            float ar[TM], br[TN];
            #pragma unroll
            for (int i = 0; i < TM; i++) ar[i] = As[k][tm + i];
            #pragma unroll
            for (int j = 0; j < TN; j++) br[j] = Bs[k][tn + j];
            #pragma unroll
            for (int i = 0; i < TM; i++)
                #pragma unroll
                for (int j = 0; j < TN; j++)
                    acc[i][j] += ar[i] * br[j];
        }
        __syncthreads();
    }

    // Epilogue: add bias, store
    #pragma unroll
    for (int i = 0; i < TM; i++) {
        int gr = block_m + tm + i;
        if (gr >= M) break;
        #pragma unroll
        for (int j = 0; j < TN; j += 4) {
            int gc = block_n + tn + j;
            float4 o;
            o.x = acc[i][j + 0] + bias[gc + 0];
            o.y = acc[i][j + 1] + bias[gc + 1];
            o.z = acc[i][j + 2] + bias[gc + 2];
            o.w = acc[i][j + 3] + bias[gc + 3];
            *(float4*)(C + (size_t)gr * D + gc) = o;
        }
    }
}

// ---------------------------------------------------------------------------
extern "C" void kernel_launch(void* const* d_in, const int* in_sizes, int n_in,
                              void* d_out, int out_size)
{
    const float* x      = (const float*)d_in[0];      // [50000, 512]
    const float* weight = (const float*)d_in[1];      // [512, 512]
    const float* bias   = (const float*)d_in[2];      // [512]
    const int*   src    = (const int*)d_in[3];        // [800000]
    const int*   dst    = (const int*)d_in[4];        // [800000]
    float*       out    = (float*)d_out;              // [50000, 512]

    float* agg;
    cudaGetSymbolAddress((void**)&agg, g_agg);

    // Phase 1: zero agg
    size_t n4 = (size_t)N_NODES * D / 4;            // 6.4M float4
    zero_kernel<<<(unsigned)((n4 + 255) / 256), 256>>>(n4);

    // Phase 2: scatter-add (one warp per edge)
    {
        size_t total_threads = (size_t)N_EDGES * 32;
        unsigned blocks = (unsigned)((total_threads + 255) / 256);
        scatter_kernel<<<blocks, 256>>>(x, src, dst);
    }

    // Phase 3: GEMM + bias
    {
        dim3 grid(D / BN, (N_NODES + BM - 1) / BM); // (4, 391)
        gemm_kernel<<<grid, 256>>>(agg, weight, bias, out, N_NODES);
    }
}

// round 4
// speedup vs baseline: 1.4044x; 1.4044x over previous
#include <cuda_runtime.h>
#include <cuda_bf16.h>
#include <stdint.h>

// GCNConvDGL: out = segment_sum(x[src] -> dst) @ W + bias
// bf16-split GEMM on mma.sync (HMMA) — tcgen05 unavailable at compute_103.

#define N_NODES 50000
#define N_EDGES 800000
#define D       512
#define M_PAD   50048          // 391 * 128

// ---------------- scratch (static device globals; zero-init at load) --------
__device__ float          g_agg[(size_t)N_NODES * D];        // 102.4 MB
__device__ __nv_bfloat16  g_a_hi[(size_t)M_PAD * D];         // 51.2 MB
__device__ __nv_bfloat16  g_a_lo[(size_t)M_PAD * D];         // 51.2 MB
__device__ __nv_bfloat16  g_wt_hi[(size_t)D * D];            // W^T hi
__device__ __nv_bfloat16  g_wt_lo[(size_t)D * D];            // W^T lo

// ---------------- PTX helpers (all sm_80+ base features) ----------------
__device__ __forceinline__ uint32_t smem_u32(const void* p) {
    uint32_t a;
    asm("{ .reg .u64 t; cvta.to.shared.u64 t, %1; cvt.u32.u64 %0, t; }"
        : "=r"(a) : "l"(p));
    return a;
}
__device__ __forceinline__ void cp_async16(uint32_t saddr, const void* gaddr) {
    asm volatile("cp.async.cg.shared.global [%0], [%1], 16;"
                 :: "r"(saddr), "l"(gaddr) : "memory");
}
__device__ __forceinline__ void cp_commit() {
    asm volatile("cp.async.commit_group;" ::: "memory");
}
template <int N> __device__ __forceinline__ void cp_wait() {
    asm volatile("cp.async.wait_group %0;" :: "n"(N) : "memory");
}
__device__ __forceinline__ void ldm_x4(uint32_t* r, uint32_t saddr) {
    asm volatile("ldmatrix.sync.aligned.m8n8.x4.shared.b16 {%0,%1,%2,%3}, [%4];"
                 : "=r"(r[0]), "=r"(r[1]), "=r"(r[2]), "=r"(r[3])
                 : "r"(saddr));
}
__device__ __forceinline__ void mma_bf16(float* c, const uint32_t* a,
                                         uint32_t b0, uint32_t b1) {
    asm volatile(
        "mma.sync.aligned.m16n8k16.row.col.f32.bf16.bf16.f32 "
        "{%0,%1,%2,%3}, {%4,%5,%6,%7}, {%8,%9}, {%0,%1,%2,%3};"
        : "+f"(c[0]), "+f"(c[1]), "+f"(c[2]), "+f"(c[3])
        : "r"(a[0]), "r"(a[1]), "r"(a[2]), "r"(a[3]), "r"(b0), "r"(b1));
}

// ---------------------------------------------------------------------------
// Phase 1: zero the aggregation buffer
// ---------------------------------------------------------------------------
__global__ void zero_kernel(size_t n4) {
    size_t i = (size_t)blockIdx.x * blockDim.x + threadIdx.x;
    if (i < n4) ((float4*)g_agg)[i] = make_float4(0.f, 0.f, 0.f, 0.f);
}

// ---------------------------------------------------------------------------
// Phase 2: scatter-add, one warp per edge, red.global.add.v4.f32
// ---------------------------------------------------------------------------
__global__ void __launch_bounds__(256) scatter_kernel(
    const float* __restrict__ x,
    const int* __restrict__ src,
    const int* __restrict__ dst)
{
    int warp = (int)((blockIdx.x * (size_t)blockDim.x + threadIdx.x) >> 5);
    int lane = threadIdx.x & 31;
    if (warp >= N_EDGES) return;

    int s = src[warp];
    int d = dst[warp];
    const float4* xr = (const float4*)(x + (size_t)s * D);
    float* ar = g_agg + (size_t)d * D;

    #pragma unroll
    for (int i = 0; i < 4; i++) {
        int c4 = lane + i * 32;
        float4 v = xr[c4];
        asm volatile("red.global.add.v4.f32 [%0], {%1, %2, %3, %4};"
                     :: "l"(ar + c4 * 4), "f"(v.x), "f"(v.y), "f"(v.z), "f"(v.w)
                     : "memory");
    }
}

// ---------------------------------------------------------------------------
// Phase 3a: convert agg fp32 -> bf16 hi/lo split
// ---------------------------------------------------------------------------
__global__ void __launch_bounds__(256) convert_a_kernel() {
    size_t i = ((size_t)blockIdx.x * blockDim.x + threadIdx.x) * 4;
    if (i >= (size_t)N_NODES * D) return;
    float4 v = *(const float4*)(g_agg + i);
    __nv_bfloat16 h[4], l[4];
    float f[4] = {v.x, v.y, v.z, v.w};
    #pragma unroll
    for (int j = 0; j < 4; j++) {
        h[j] = __float2bfloat16_rn(f[j]);
        l[j] = __float2bfloat16_rn(f[j] - __bfloat162float(h[j]));
    }
    *(uint2*)(g_a_hi + i) = *(uint2*)h;
    *(uint2*)(g_a_lo + i) = *(uint2*)l;
}

// ---------------------------------------------------------------------------
// Phase 3b: convert + transpose W fp32 [K,N] -> Wt hi/lo bf16 [N,K]
// ---------------------------------------------------------------------------
__global__ void __launch_bounds__(256) convert_w_kernel(const float* __restrict__ W) {
    int idx = blockIdx.x * blockDim.x + threadIdx.x;
    if (idx >= D * D) return;
    int k = idx >> 9, n = idx & 511;
    float w = W[idx];
    __nv_bfloat16 h = __float2bfloat16_rn(w);
    __nv_bfloat16 l = __float2bfloat16_rn(w - __bfloat162float(h));
    g_wt_hi[(size_t)n * D + k] = h;
    g_wt_lo[(size_t)n * D + k] = l;
}

// ---------------------------------------------------------------------------
// Phase 4: mma.sync bf16-split GEMM
// C[M,512] = (A_hi+A_lo) @ (W^T_hi+W^T_lo)^T + bias   (3 products, fp32 acc)
// CTA 128x128, BK=32, 3-stage cp.async pipeline, 8 warps, warp tile 64x32.
// ---------------------------------------------------------------------------
#define BK      32
#define KP      40                    // padded smem row stride (elements)
#define TILE_B  (128 * KP * 2)        // 10240 B per tile
#define STAGE_B (4 * TILE_B)          // Ah, Al, Bh, Bl = 40960 B
#define STAGES  3
#define SMEM_TOTAL (STAGES * STAGE_B) // 122880 B
#define NK      (D / BK)              // 16

__global__ void __launch_bounds__(256, 1) gemm_mma_kernel(
    const float* __restrict__ bias,
    float* __restrict__ C)
{
    extern __shared__ char smem[];
    const uint32_t smem_base = smem_u32(smem);
    const int tid  = threadIdx.x;
    const int wid  = tid >> 5;
    const int lane = tid & 31;
    const int wm   = wid >> 2;        // 0..1  (64 rows each)
    const int wn   = wid & 3;         // 0..3  (32 cols each)
    const int block_m = blockIdx.y * 128;
    const int block_n = blockIdx.x * 128;

    // ---- tile loader: one K-chunk (4 tiles) into a stage ----
    auto load_chunk = [&](int kt, int stage) {
        const int k0 = kt * BK;
        const uint32_t sb = smem_base + stage * STAGE_B;
        #pragma unroll
        for (int it = 0; it < 8; it++) {
            const int cid  = it * 256 + tid;      // 0..2047
            const int tile = cid >> 9;            // 0..3
            const int r    = (cid >> 2) & 127;
            const int c4   = cid & 3;
            const __nv_bfloat16* g;
            if (tile == 0)      g = g_a_hi  + (size_t)(block_m + r) * D;
            else if (tile == 1) g = g_a_lo  + (size_t)(block_m + r) * D;
            else if (tile == 2) g = g_wt_hi + (size_t)(block_n + r) * D;
            else                g = g_wt_lo + (size_t)(block_n + r) * D;
            cp_async16(sb + tile * TILE_B + r * (KP * 2) + c4 * 16,
                       g + k0 + c4 * 8);
        }
        cp_commit();
    };

    float acc[4][4][4];
    #pragma unroll
    for (int i = 0; i < 4; i++)
        #pragma unroll
        for (int j = 0; j < 4; j++)
            #pragma unroll
            for (int e = 0; e < 4; e++)
                acc[i][j][e] = 0.f;

    // prologue
    load_chunk(0, 0);
    load_chunk(1, 1);

    // ldmatrix per-lane offsets (same pattern for A and B tiles)
    const uint32_t row_off = (uint32_t)(lane & 15) * (KP * 2);
    const uint32_t k_lane  = (uint32_t)((lane >> 4) << 4);   // 0 or 16 bytes

    for (int kt = 0; kt < NK; kt++) {
        if (kt >= NK - 1) cp_wait<0>(); else cp_wait<1>();
        __syncthreads();

        if (kt + 2 < NK) load_chunk(kt + 2, (kt + 2) % STAGES);

        const uint32_t sb  = smem_base + (kt % STAGES) * STAGE_B;
        const uint32_t aH0 = sb + 0 * TILE_B + (wm * 64) * (KP * 2) + row_off;
        const uint32_t aL0 = sb + 1 * TILE_B + (wm * 64) * (KP * 2) + row_off;
        const uint32_t bH0 = sb + 2 * TILE_B + (wn * 32) * (KP * 2) + row_off;
        const uint32_t bL0 = sb + 3 * TILE_B + (wn * 32) * (KP * 2) + row_off;

        #pragma unroll
        for (int ks = 0; ks < 2; ks++) {
            const uint32_t koff = ks * 32 + k_lane;   // bytes
            uint32_t aH[4][4], aL[4][4], bH[2][4], bL[2][4];
            #pragma unroll
            for (int mt = 0; mt < 4; mt++) {
                ldm_x4(aH[mt], aH0 + mt * 16 * (KP * 2) + koff);
                ldm_x4(aL[mt], aL0 + mt * 16 * (KP * 2) + koff);
            }
            #pragma unroll
            for (int np = 0; np < 2; np++) {
                ldm_x4(bH[np], bH0 + np * 16 * (KP * 2) + koff);
                ldm_x4(bL[np], bL0 + np * 16 * (KP * 2) + koff);
            }
            #pragma unroll
            for (int mt = 0; mt < 4; mt++) {
                #pragma unroll
                for (int nt = 0; nt < 4; nt++) {
                    const int np = nt >> 1, sel = nt & 1;
                    mma_bf16(acc[mt][nt], aH[mt], bH[np][sel], bH[np][sel + 2]);
                    mma_bf16(acc[mt][nt], aH[mt], bL[np][sel], bL[np][sel + 2]);
                    mma_bf16(acc[mt][nt], aL[mt], bH[np][sel], bH[np][sel + 2]);
                }
            }
        }
        __syncthreads();
    }

    // ---- epilogue: bias + store ----
    #pragma unroll
    for (int nt = 0; nt < 4; nt++) {
        const int col = block_n + wn * 32 + nt * 8 + (lane & 3) * 2;
        const float2 bv = *(const float2*)(bias + col);
        #pragma unroll
        for (int mt = 0; mt < 4; mt++) {
            const int r0 = block_m + wm * 64 + mt * 16 + (lane >> 2);
            const int r1 = r0 + 8;
            if (r0 < N_NODES) {
                float2 o = make_float2(acc[mt][nt][0] + bv.x,
                                       acc[mt][nt][1] + bv.y);
                *(float2*)(C + (size_t)r0 * D + col) = o;
            }
            if (r1 < N_NODES) {
                float2 o = make_float2(acc[mt][nt][2] + bv.x,
                                       acc[mt][nt][3] + bv.y);
                *(float2*)(C + (size_t)r1 * D + col) = o;
            }
        }
    }
}

// ---------------------------------------------------------------------------
extern "C" void kernel_launch(void* const* d_in, const int* in_sizes, int n_in,
                              void* d_out, int out_size)
{
    const float* x      = (const float*)d_in[0];
    const float* weight = (const float*)d_in[1];
    const float* bias   = (const float*)d_in[2];
    const int*   src    = (const int*)d_in[3];
    const int*   dst    = (const int*)d_in[4];
    float*       out    = (float*)d_out;

    // Phase 1: zero agg
    size_t n4 = (size_t)N_NODES * D / 4;
    zero_kernel<<<(unsigned)((n4 + 255) / 256), 256>>>(n4);

    // Phase 2: scatter-add
    {
        size_t total_threads = (size_t)N_EDGES * 32;
        unsigned blocks = (unsigned)((total_threads + 255) / 256);
        scatter_kernel<<<blocks, 256>>>(x, src, dst);
    }

    // Phase 3: converts
    {
        size_t nthr = (size_t)N_NODES * D / 4;
        convert_a_kernel<<<(unsigned)((nthr + 255) / 256), 256>>>();
        convert_w_kernel<<<(D * D + 255) / 256, 256>>>(weight);
    }

    // Phase 4: mma.sync GEMM + bias
    {
        static bool attr_set = false;
        if (!attr_set) {
            cudaFuncSetAttribute(gemm_mma_kernel,
                                 cudaFuncAttributeMaxDynamicSharedMemorySize,
                                 SMEM_TOTAL);
            attr_set = true;
        }
        dim3 grid(D / 128, M_PAD / 128);  // (4, 391)
        gemm_mma_kernel<<<grid, 256, SMEM_TOTAL>>>(bias, out);
    }
}

// round 5
// speedup vs baseline: 2.0499x; 1.4597x over previous
#include <cuda_runtime.h>
#include <cuda_bf16.h>
#include <stdint.h>

// GCNConvDGL: out = segment_sum(x[src] -> dst) @ W + bias
// CSR two-phase aggregation (no feature atomics) + bf16-split mma.sync GEMM.

#define N_NODES 50000
#define N_EDGES 800000
#define D       512
#define M_PAD   50048          // 391 * 128

// ---------------- scratch (static device globals) ----------------
__device__ __nv_bfloat16  g_a_hi[(size_t)M_PAD * D];         // 51.2 MB
__device__ __nv_bfloat16  g_a_lo[(size_t)M_PAD * D];         // 51.2 MB
__device__ __nv_bfloat16  g_wt_hi[(size_t)D * D];            // W^T hi
__device__ __nv_bfloat16  g_wt_lo[(size_t)D * D];            // W^T lo
__device__ int            g_cnt[N_NODES];                    // degree histogram
__device__ int            g_row[N_NODES + 1];                // CSR row offsets
__device__ int            g_work[N_NODES];                   // scatter cursors
__device__ int            g_csr[N_EDGES];                    // src ids by dst

// ---------------- PTX helpers (sm_80+ base features only) ----------------
__device__ __forceinline__ uint32_t smem_u32(const void* p) {
    uint32_t a;
    asm("{ .reg .u64 t; cvta.to.shared.u64 t, %1; cvt.u32.u64 %0, t; }"
        : "=r"(a) : "l"(p));
    return a;
}
__device__ __forceinline__ void cp_async16(uint32_t saddr, const void* gaddr) {
    asm volatile("cp.async.cg.shared.global [%0], [%1], 16;"
                 :: "r"(saddr), "l"(gaddr) : "memory");
}
__device__ __forceinline__ void cp_commit() {
    asm volatile("cp.async.commit_group;" ::: "memory");
}
template <int N> __device__ __forceinline__ void cp_wait() {
    asm volatile("cp.async.wait_group %0;" :: "n"(N) : "memory");
}
__device__ __forceinline__ void ldm_x4(uint32_t* r, uint32_t saddr) {
    asm volatile("ldmatrix.sync.aligned.m8n8.x4.shared.b16 {%0,%1,%2,%3}, [%4];"
                 : "=r"(r[0]), "=r"(r[1]), "=r"(r[2]), "=r"(r[3])
                 : "r"(saddr));
}
__device__ __forceinline__ void mma_bf16(float* c, const uint32_t* a,
                                         uint32_t b0, uint32_t b1) {
    asm volatile(
        "mma.sync.aligned.m16n8k16.row.col.f32.bf16.bf16.f32 "
        "{%0,%1,%2,%3}, {%4,%5,%6,%7}, {%8,%9}, {%0,%1,%2,%3};"
        : "+f"(c[0]), "+f"(c[1]), "+f"(c[2]), "+f"(c[3])
        : "r"(a[0]), "r"(a[1]), "r"(a[2]), "r"(a[3]), "r"(b0), "r"(b1));
}

// ---------------------------------------------------------------------------
// CSR build step 1: zero histogram
// ---------------------------------------------------------------------------
__global__ void zero_cnt_kernel() {
    int i = blockIdx.x * blockDim.x + threadIdx.x;
    if (i < N_NODES) g_cnt[i] = 0;
}

// CSR build step 2: degree histogram over dst
__global__ void __launch_bounds__(256) hist_kernel(const int* __restrict__ dst) {
    int e = blockIdx.x * blockDim.x + threadIdx.x;
    if (e < N_EDGES) atomicAdd(&g_cnt[dst[e]], 1);
}

// CSR build step 3: exclusive scan (single block, 1024 threads)
__global__ void __launch_bounds__(1024) scan_kernel() {
    __shared__ int partial[1024];
    const int T = 1024;
    const int CHUNK = (N_NODES + T - 1) / T;   // 49
    int tid = threadIdx.x;
    int base = tid * CHUNK;

    int sum = 0;
    for (int i = 0; i < CHUNK; i++) {
        int idx = base + i;
        if (idx < N_NODES) sum += g_cnt[idx];
    }
    partial[tid] = sum;
    __syncthreads();

    // Hillis-Steele inclusive scan
    for (int off = 1; off < T; off <<= 1) {
        int t = (tid >= off) ? partial[tid - off] : 0;
        __syncthreads();
        partial[tid] += t;
        __syncthreads();
    }

    int run = (tid == 0) ? 0 : partial[tid - 1];
    for (int i = 0; i < CHUNK; i++) {
        int idx = base + i;
        if (idx < N_NODES) {
            g_row[idx]  = run;
            g_work[idx] = run;
            run += g_cnt[idx];
        }
    }
    if (tid == T - 1) g_row[N_NODES] = run;
}

// CSR build step 4: scatter src ids into buckets
__global__ void __launch_bounds__(256) scatter_csr_kernel(
    const int* __restrict__ src, const int* __restrict__ dst)
{
    int e = blockIdx.x * blockDim.x + threadIdx.x;
    if (e < N_EDGES) {
        int pos = atomicAdd(&g_work[dst[e]], 1);
        g_csr[pos] = src[e];
    }
}

// ---------------------------------------------------------------------------
// Aggregation: one 128-thread block per (padded) node row.
// Gathers x rows per CSR list, accumulates float4 in registers, writes the
// row once as bf16 hi/lo split. Pad rows write zeros.
// ---------------------------------------------------------------------------
__global__ void __launch_bounds__(128) agg_kernel(const float* __restrict__ x) {
    const int node = blockIdx.x;
    const int tid  = threadIdx.x;

    float4 acc = make_float4(0.f, 0.f, 0.f, 0.f);

    if (node < N_NODES) {
        const int s0 = g_row[node];
        const int s1 = g_row[node + 1];
        int e = s0;
        // unroll by 2 for MLP
        for (; e + 1 < s1; e += 2) {
            int sa = __ldg(&g_csr[e]);
            int sb = __ldg(&g_csr[e + 1]);
            float4 va = __ldg((const float4*)(x + (size_t)sa * D) + tid);
            float4 vb = __ldg((const float4*)(x + (size_t)sb * D) + tid);
            acc.x += va.x; acc.y += va.y; acc.z += va.z; acc.w += va.w;
            acc.x += vb.x; acc.y += vb.y; acc.z += vb.z; acc.w += vb.w;
        }
        if (e < s1) {
            int sa = __ldg(&g_csr[e]);
            float4 va = __ldg((const float4*)(x + (size_t)sa * D) + tid);
            acc.x += va.x; acc.y += va.y; acc.z += va.z; acc.w += va.w;
        }
    }

    // split fp32 -> bf16 hi/lo, one 8B store per array
    float f[4] = {acc.x, acc.y, acc.z, acc.w};
    __nv_bfloat16 h[4], l[4];
    #pragma unroll
    for (int j = 0; j < 4; j++) {
        h[j] = __float2bfloat16_rn(f[j]);
        l[j] = __float2bfloat16_rn(f[j] - __bfloat162float(h[j]));
    }
    size_t off = (size_t)node * D + tid * 4;
    *(uint2*)(g_a_hi + off) = *(uint2*)h;
    *(uint2*)(g_a_lo + off) = *(uint2*)l;
}

// ---------------------------------------------------------------------------
// Convert + transpose W fp32 [K,N] -> Wt hi/lo bf16 [N,K]
// ---------------------------------------------------------------------------
__global__ void __launch_bounds__(256) convert_w_kernel(const float* __restrict__ W) {
    int idx = blockIdx.x * blockDim.x + threadIdx.x;
    if (idx >= D * D) return;
    int k = idx >> 9, n = idx & 511;
    float w = W[idx];
    __nv_bfloat16 h = __float2bfloat16_rn(w);
    __nv_bfloat16 l = __float2bfloat16_rn(w - __bfloat162float(h));
    g_wt_hi[(size_t)n * D + k] = h;
    g_wt_lo[(size_t)n * D + k] = l;
}

// ---------------------------------------------------------------------------
// mma.sync bf16-split GEMM: C = (A_hi+A_lo)(W_hi+W_lo) + bias  (3 products)
// CTA 128x128, BK=32, 3-stage cp.async pipeline, 8 warps, warp tile 64x32.
// ---------------------------------------------------------------------------
#define BK      32
#define KP      40                    // padded smem row stride (elements)
#define TILE_B  (128 * KP * 2)        // 10240 B per tile
#define STAGE_B (4 * TILE_B)          // Ah, Al, Bh, Bl = 40960 B
#define STAGES  3
#define SMEM_TOTAL (STAGES * STAGE_B) // 122880 B
#define NK      (D / BK)              // 16

__global__ void __launch_bounds__(256, 1) gemm_mma_kernel(
    const float* __restrict__ bias,
    float* __restrict__ C)
{
    extern __shared__ char smem[];
    const uint32_t smem_base = smem_u32(smem);
    const int tid  = threadIdx.x;
    const int wid  = tid >> 5;
    const int lane = tid & 31;
    const int wm   = wid >> 2;        // 0..1  (64 rows each)
    const int wn   = wid & 3;         // 0..3  (32 cols each)
    const int block_m = blockIdx.y * 128;
    const int block_n = blockIdx.x * 128;

    auto load_chunk = [&](int kt, int stage) {
        const int k0 = kt * BK;
        const uint32_t sb = smem_base + stage * STAGE_B;
        #pragma unroll
        for (int it = 0; it < 8; it++) {
            const int cid  = it * 256 + tid;      // 0..2047
            const int tile = cid >> 9;            // 0..3
            const int r    = (cid >> 2) & 127;
            const int c4   = cid & 3;
            const __nv_bfloat16* g;
            if (tile == 0)      g = g_a_hi  + (size_t)(block_m + r) * D;
            else if (tile == 1) g = g_a_lo  + (size_t)(block_m + r) * D;
            else if (tile == 2) g = g_wt_hi + (size_t)(block_n + r) * D;
            else                g = g_wt_lo + (size_t)(block_n + r) * D;
            cp_async16(sb + tile * TILE_B + r * (KP * 2) + c4 * 16,
                       g + k0 + c4 * 8);
        }
        cp_commit();
    };

    float acc[4][4][4];
    #pragma unroll
    for (int i = 0; i < 4; i++)
        #pragma unroll
        for (int j = 0; j < 4; j++)
            #pragma unroll
            for (int e = 0; e < 4; e++)
                acc[i][j][e] = 0.f;

    load_chunk(0, 0);
    load_chunk(1, 1);

    const uint32_t row_off = (uint32_t)(lane & 15) * (KP * 2);
    const uint32_t k_lane  = (uint32_t)((lane >> 4) << 4);   // 0 or 16 bytes

    for (int kt = 0; kt < NK; kt++) {
        if (kt >= NK - 1) cp_wait<0>(); else cp_wait<1>();
        __syncthreads();

        if (kt + 2 < NK) load_chunk(kt + 2, (kt + 2) % STAGES);

        const uint32_t sb  = smem_base + (kt % STAGES) * STAGE_B;
        const uint32_t aH0 = sb + 0 * TILE_B + (wm * 64) * (KP * 2) + row_off;
        const uint32_t aL0 = sb + 1 * TILE_B + (wm * 64) * (KP * 2) + row_off;
        const uint32_t bH0 = sb + 2 * TILE_B + (wn * 32) * (KP * 2) + row_off;
        const uint32_t bL0 = sb + 3 * TILE_B + (wn * 32) * (KP * 2) + row_off;

        #pragma unroll
        for (int ks = 0; ks < 2; ks++) {
            const uint32_t koff = ks * 32 + k_lane;   // bytes
            uint32_t aH[4][4], aL[4][4], bH[2][4], bL[2][4];
            #pragma unroll
            for (int mt = 0; mt < 4; mt++) {
                ldm_x4(aH[mt], aH0 + mt * 16 * (KP * 2) + koff);
                ldm_x4(aL[mt], aL0 + mt * 16 * (KP * 2) + koff);
            }
            #pragma unroll
            for (int np = 0; np < 2; np++) {
                ldm_x4(bH[np], bH0 + np * 16 * (KP * 2) + koff);
                ldm_x4(bL[np], bL0 + np * 16 * (KP * 2) + koff);
            }
            #pragma unroll
            for (int mt = 0; mt < 4; mt++) {
                #pragma unroll
                for (int nt = 0; nt < 4; nt++) {
                    const int np = nt >> 1, sel = nt & 1;
                    mma_bf16(acc[mt][nt], aH[mt], bH[np][sel], bH[np][sel + 2]);
                    mma_bf16(acc[mt][nt], aH[mt], bL[np][sel], bL[np][sel + 2]);
                    mma_bf16(acc[mt][nt], aL[mt], bH[np][sel], bH[np][sel + 2]);
                }
            }
        }
        __syncthreads();
    }

    #pragma unroll
    for (int nt = 0; nt < 4; nt++) {
        const int col = block_n + wn * 32 + nt * 8 + (lane & 3) * 2;
        const float2 bv = *(const float2*)(bias + col);
        #pragma unroll
        for (int mt = 0; mt < 4; mt++) {
            const int r0 = block_m + wm * 64 + mt * 16 + (lane >> 2);
            const int r1 = r0 + 8;
            if (r0 < N_NODES) {
                float2 o = make_float2(acc[mt][nt][0] + bv.x,
                                       acc[mt][nt][1] + bv.y);
                *(float2*)(C + (size_t)r0 * D + col) = o;
            }
            if (r1 < N_NODES) {
                float2 o = make_float2(acc[mt][nt][2] + bv.x,
                                       acc[mt][nt][3] + bv.y);
                *(float2*)(C + (size_t)r1 * D + col) = o;
            }
        }
    }
}

// ---------------------------------------------------------------------------
extern "C" void kernel_launch(void* const* d_in, const int* in_sizes, int n_in,
                              void* d_out, int out_size)
{
    const float* x      = (const float*)d_in[0];
    const float* weight = (const float*)d_in[1];
    const float* bias   = (const float*)d_in[2];
    const int*   src    = (const int*)d_in[3];
    const int*   dst    = (const int*)d_in[4];
    float*       out    = (float*)d_out;

    // CSR build
    zero_cnt_kernel<<<(N_NODES + 255) / 256, 256>>>();
    hist_kernel<<<(N_EDGES + 255) / 256, 256>>>(dst);
    scan_kernel<<<1, 1024>>>();
    scatter_csr_kernel<<<(N_EDGES + 255) / 256, 256>>>(src, dst);

    // Aggregate + fused bf16 hi/lo split (covers padding rows too)
    agg_kernel<<<M_PAD, 128>>>(x);

    // Weight convert/transpose
    convert_w_kernel<<<(D * D + 255) / 256, 256>>>(weight);

    // GEMM + bias
    {
        static bool attr_set = false;
        if (!attr_set) {
            cudaFuncSetAttribute(gemm_mma_kernel,
                                 cudaFuncAttributeMaxDynamicSharedMemorySize,
                                 SMEM_TOTAL);
            attr_set = true;
        }
        dim3 grid(D / 128, M_PAD / 128);  // (4, 391)
        gemm_mma_kernel<<<grid, 256, SMEM_TOTAL>>>(bias, out);
    }
}

// round 7
// speedup vs baseline: 2.2656x; 1.1052x over previous
#include <cuda_runtime.h>
#include <cuda_bf16.h>
#include <stdint.h>

// GCNConvDGL: out = segment_sum(x[src] -> dst) @ W + bias
// CSR aggregation (no feature atomics) + bf16-split mma.sync GEMM.

#define N_NODES 50000
#define N_EDGES 800000
#define D       512
#define M_PAD   50048          // 391 * 128

// ---------------- scratch (static device globals) ----------------
__device__ __nv_bfloat16  g_a_hi[(size_t)M_PAD * D];         // 51.2 MB
__device__ __nv_bfloat16  g_a_lo[(size_t)M_PAD * D];         // 51.2 MB
__device__ __nv_bfloat16  g_wt_hi[(size_t)D * D];            // W^T hi
__device__ __nv_bfloat16  g_wt_lo[(size_t)D * D];            // W^T lo
__device__ int            g_cnt[N_NODES];
__device__ int            g_row[N_NODES + 1];
__device__ int            g_work[N_NODES];
__device__ int            g_csr[N_EDGES];

// ---------------- PTX helpers ----------------
__device__ __forceinline__ uint32_t smem_u32(const void* p) {
    uint32_t a;
    asm("{ .reg .u64 t; cvta.to.shared.u64 t, %1; cvt.u32.u64 %0, t; }"
        : "=r"(a) : "l"(p));
    return a;
}
__device__ __forceinline__ void cp_async16(uint32_t saddr, const void* gaddr) {
    asm volatile("cp.async.cg.shared.global [%0], [%1], 16;"
                 :: "r"(saddr), "l"(gaddr) : "memory");
}
__device__ __forceinline__ void cp_commit() {
    asm volatile("cp.async.commit_group;" ::: "memory");
}
template <int N> __device__ __forceinline__ void cp_wait() {
    asm volatile("cp.async.wait_group %0;" :: "n"(N) : "memory");
}
__device__ __forceinline__ void ldm_x4(uint32_t* r, uint32_t saddr) {
    asm volatile("ldmatrix.sync.aligned.m8n8.x4.shared.b16 {%0,%1,%2,%3}, [%4];"
                 : "=r"(r[0]), "=r"(r[1]), "=r"(r[2]), "=r"(r[3])
                 : "r"(saddr));
}
__device__ __forceinline__ void mma_bf16(float* c, const uint32_t* a,
                                         uint32_t b0, uint32_t b1) {
    asm volatile(
        "mma.sync.aligned.m16n8k16.row.col.f32.bf16.bf16.f32 "
        "{%0,%1,%2,%3}, {%4,%5,%6,%7}, {%8,%9}, {%0,%1,%2,%3};"
        : "+f"(c[0]), "+f"(c[1]), "+f"(c[2]), "+f"(c[3])
        : "r"(a[0]), "r"(a[1]), "r"(a[2]), "r"(a[3]), "r"(b0), "r"(b1));
}
__device__ __forceinline__ void st_cs_u2(void* p, uint2 v) {
    asm volatile("st.global.cs.v2.u32 [%0], {%1, %2};"
                 :: "l"(p), "r"(v.x), "r"(v.y) : "memory");
}

// ---------------------------------------------------------------------------
// CSR build
// ---------------------------------------------------------------------------
__global__ void zero_cnt_kernel() {
    int i = blockIdx.x * blockDim.x + threadIdx.x;
    if (i < N_NODES) g_cnt[i] = 0;
}

__global__ void __launch_bounds__(256) hist_kernel(const int* __restrict__ dst) {
    int e = blockIdx.x * blockDim.x + threadIdx.x;
    if (e < N_EDGES) atomicAdd(&g_cnt[dst[e]], 1);
}

__global__ void __launch_bounds__(1024) scan_kernel() {
    __shared__ int partial[1024];
    const int T = 1024;
    const int CHUNK = (N_NODES + T - 1) / T;   // 49
    int tid = threadIdx.x;
    int base = tid * CHUNK;

    int sum = 0;
    for (int i = 0; i < CHUNK; i++) {
        int idx = base + i;
        if (idx < N_NODES) sum += g_cnt[idx];
    }
    partial[tid] = sum;
    __syncthreads();

    for (int off = 1; off < T; off <<= 1) {
        int t = (tid >= off) ? partial[tid - off] : 0;
        __syncthreads();
        partial[tid] += t;
        __syncthreads();
    }

    int run = (tid == 0) ? 0 : partial[tid - 1];
    for (int i = 0; i < CHUNK; i++) {
        int idx = base + i;
        if (idx < N_NODES) {
            g_row[idx]  = run;
            g_work[idx] = run;
            run += g_cnt[idx];
        }
    }
    if (tid == T - 1) g_row[N_NODES] = run;
}

__global__ void __launch_bounds__(256) scatter_csr_kernel(
    const int* __restrict__ src, const int* __restrict__ dst)
{
    int e = blockIdx.x * blockDim.x + threadIdx.x;
    if (e < N_EDGES) {
        int pos = atomicAdd(&g_work[dst[e]], 1);
        g_csr[pos] = src[e];
    }
}

// ---------------------------------------------------------------------------
// Aggregation: one 128-thread block per node; unroll 4 for MLP; streaming
// stores for hi/lo (keep x resident in L2).
// ---------------------------------------------------------------------------
__global__ void __launch_bounds__(128) agg_kernel(const float* __restrict__ x) {
    const int node = blockIdx.x;
    const int tid  = threadIdx.x;

    float4 acc = make_float4(0.f, 0.f, 0.f, 0.f);

    if (node < N_NODES) {
        const int s0 = g_row[node];
        const int s1 = g_row[node + 1];
        int e = s0;
        for (; e + 3 < s1; e += 4) {
            int sa = __ldg(&g_csr[e]);
            int sb = __ldg(&g_csr[e + 1]);
            int sc = __ldg(&g_csr[e + 2]);
            int sd = __ldg(&g_csr[e + 3]);
            float4 va = __ldg((const float4*)(x + (size_t)sa * D) + tid);
            float4 vb = __ldg((const float4*)(x + (size_t)sb * D) + tid);
            float4 vc = __ldg((const float4*)(x + (size_t)sc * D) + tid);
            float4 vd = __ldg((const float4*)(x + (size_t)sd * D) + tid);
            acc.x += va.x; acc.y += va.y; acc.z += va.z; acc.w += va.w;
            acc.x += vb.x; acc.y += vb.y; acc.z += vb.z; acc.w += vb.w;
            acc.x += vc.x; acc.y += vc.y; acc.z += vc.z; acc.w += vc.w;
            acc.x += vd.x; acc.y += vd.y; acc.z += vd.z; acc.w += vd.w;
        }
        for (; e < s1; e++) {
            int sa = __ldg(&g_csr[e]);
            float4 va = __ldg((const float4*)(x + (size_t)sa * D) + tid);
            acc.x += va.x; acc.y += va.y; acc.z += va.z; acc.w += va.w;
        }
    }

    float f[4] = {acc.x, acc.y, acc.z, acc.w};
    __nv_bfloat16 h[4], l[4];
    #pragma unroll
    for (int j = 0; j < 4; j++) {
        h[j] = __float2bfloat16_rn(f[j]);
        l[j] = __float2bfloat16_rn(f[j] - __bfloat162float(h[j]));
    }
    size_t off = (size_t)node * D + tid * 4;
    st_cs_u2(g_a_hi + off, *(uint2*)h);
    st_cs_u2(g_a_lo + off, *(uint2*)l);
}

// ---------------------------------------------------------------------------
// Convert + transpose W fp32 [K,N] -> Wt hi/lo bf16 [N,K]
// ---------------------------------------------------------------------------
__global__ void __launch_bounds__(256) convert_w_kernel(const float* __restrict__ W) {
    int idx = blockIdx.x * blockDim.x + threadIdx.x;
    if (idx >= D * D) return;
    int k = idx >> 9, n = idx & 511;
    float w = W[idx];
    __nv_bfloat16 h = __float2bfloat16_rn(w);
    __nv_bfloat16 l = __float2bfloat16_rn(w - __bfloat162float(h));
    g_wt_hi[(size_t)n * D + k] = h;
    g_wt_lo[(size_t)n * D + k] = l;
}

// ---------------------------------------------------------------------------
// mma.sync bf16-split GEMM: C = (A_hi+A_lo)(W_hi+W_lo) + bias  (3 products)
// CTA 128x128, BK=32, correct 2-stage double buffer (depth-1 prefetch,
// two syncs per iteration), 8 warps, warp tile 64x32, 2 CTAs/SM.
// ---------------------------------------------------------------------------
#define BK      32
#define KP      40                    // padded smem row stride (elements)
#define TILE_B  (128 * KP * 2)        // 10240 B per tile
#define STAGE_B (4 * TILE_B)          // Ah, Al, Bh, Bl = 40960 B
#define STAGES  2
#define SMEM_TOTAL (STAGES * STAGE_B) // 81920 B
#define NK      (D / BK)              // 16

__global__ void __launch_bounds__(256, 2) gemm_mma_kernel(
    const float* __restrict__ bias,
    float* __restrict__ C)
{
    extern __shared__ char smem[];
    const uint32_t smem_base = smem_u32(smem);
    const int tid  = threadIdx.x;
    const int wid  = tid >> 5;
    const int lane = tid & 31;
    const int wm   = wid >> 2;        // 0..1  (64 rows each)
    const int wn   = wid & 3;         // 0..3  (32 cols each)
    const int block_m = blockIdx.y * 128;
    const int block_n = blockIdx.x * 128;

    auto load_chunk = [&](int kt, int stage) {
        const int k0 = kt * BK;
        const uint32_t sb = smem_base + stage * STAGE_B;
        #pragma unroll
        for (int it = 0; it < 8; it++) {
            const int cid  = it * 256 + tid;      // 0..2047
            const int tile = cid >> 9;            // 0..3
            const int r    = (cid >> 2) & 127;
            const int c4   = cid & 3;
            const __nv_bfloat16* g;
            if (tile == 0)      g = g_a_hi  + (size_t)(block_m + r) * D;
            else if (tile == 1) g = g_a_lo  + (size_t)(block_m + r) * D;
            else if (tile == 2) g = g_wt_hi + (size_t)(block_n + r) * D;
            else                g = g_wt_lo + (size_t)(block_n + r) * D;
            cp_async16(sb + tile * TILE_B + r * (KP * 2) + c4 * 16,
                       g + k0 + c4 * 8);
        }
        cp_commit();
    };

    float acc[4][4][4];
    #pragma unroll
    for (int i = 0; i < 4; i++)
        #pragma unroll
        for (int j = 0; j < 4; j++)
            #pragma unroll
            for (int e = 0; e < 4; e++)
                acc[i][j][e] = 0.f;

    load_chunk(0, 0);

    const uint32_t row_off = (uint32_t)(lane & 15) * (KP * 2);
    const uint32_t k_lane  = (uint32_t)((lane >> 4) << 4);   // 0 or 16 bytes

    for (int kt = 0; kt < NK; kt++) {
        // Prefetch next chunk into the OTHER buffer. Safe: its last compute
        // (iteration kt-1) is separated from this write by the barrier at
        // the end of iteration kt-1.
        if (kt + 1 < NK) {
            load_chunk(kt + 1, (kt + 1) & 1);
            cp_wait<1>();     // wait for chunk kt (all but the newest group)
        } else {
            cp_wait<0>();
        }
        __syncthreads();      // chunk kt visible to all warps

        const uint32_t sb  = smem_base + (kt & 1) * STAGE_B;
        const uint32_t aH0 = sb + 0 * TILE_B + (wm * 64) * (KP * 2) + row_off;
        const uint32_t aL0 = sb + 1 * TILE_B + (wm * 64) * (KP * 2) + row_off;
        const uint32_t bH0 = sb + 2 * TILE_B + (wn * 32) * (KP * 2) + row_off;
        const uint32_t bL0 = sb + 3 * TILE_B + (wn * 32) * (KP * 2) + row_off;

        #pragma unroll
        for (int ks = 0; ks < 2; ks++) {
            const uint32_t koff = ks * 32 + k_lane;   // bytes
            uint32_t bH[2][4], bL[2][4];
            #pragma unroll
            for (int np = 0; np < 2; np++) {
                ldm_x4(bH[np], bH0 + np * 16 * (KP * 2) + koff);
                ldm_x4(bL[np], bL0 + np * 16 * (KP * 2) + koff);
            }
            #pragma unroll
            for (int mt = 0; mt < 4; mt++) {
                uint32_t aH[4], aL[4];
                ldm_x4(aH, aH0 + mt * 16 * (KP * 2) + koff);
                ldm_x4(aL, aL0 + mt * 16 * (KP * 2) + koff);
                #pragma unroll
                for (int nt = 0; nt < 4; nt++) {
                    const int np = nt >> 1, sel = nt & 1;
                    mma_bf16(acc[mt][nt], aH, bH[np][sel], bH[np][sel + 2]);
                    mma_bf16(acc[mt][nt], aH, bL[np][sel], bL[np][sel + 2]);
                    mma_bf16(acc[mt][nt], aL, bH[np][sel], bH[np][sel + 2]);
                }
            }
        }
        __syncthreads();      // all warps done with buffer kt&1 before it is
                              // overwritten by load_chunk(kt+2) next iteration
    }

    #pragma unroll
    for (int nt = 0; nt < 4; nt++) {
        const int col = block_n + wn * 32 + nt * 8 + (lane & 3) * 2;
        const float2 bv = *(const float2*)(bias + col);
        #pragma unroll
        for (int mt = 0; mt < 4; mt++) {
            const int r0 = block_m + wm * 64 + mt * 16 + (lane >> 2);
            const int r1 = r0 + 8;
            if (r0 < N_NODES) {
                float2 o = make_float2(acc[mt][nt][0] + bv.x,
                                       acc[mt][nt][1] + bv.y);
                *(float2*)(C + (size_t)r0 * D + col) = o;
            }
            if (r1 < N_NODES) {
                float2 o = make_float2(acc[mt][nt][2] + bv.x,
                                       acc[mt][nt][3] + bv.y);
                *(float2*)(C + (size_t)r1 * D + col) = o;
            }
        }
    }
}

// ---------------------------------------------------------------------------
extern "C" void kernel_launch(void* const* d_in, const int* in_sizes, int n_in,
                              void* d_out, int out_size)
{
    const float* x      = (const float*)d_in[0];
    const float* weight = (const float*)d_in[1];
    const float* bias   = (const float*)d_in[2];
    const int*   src    = (const int*)d_in[3];
    const int*   dst    = (const int*)d_in[4];
    float*       out    = (float*)d_out;

    // CSR build
    zero_cnt_kernel<<<(N_NODES + 255) / 256, 256>>>();
    hist_kernel<<<(N_EDGES + 255) / 256, 256>>>(dst);
    scan_kernel<<<1, 1024>>>();
    scatter_csr_kernel<<<(N_EDGES + 255) / 256, 256>>>(src, dst);

    // Aggregate + fused bf16 hi/lo split
    agg_kernel<<<M_PAD, 128>>>(x);

    // Weight convert/transpose
    convert_w_kernel<<<(D * D + 255) / 256, 256>>>(weight);

    // GEMM + bias
    {
        static bool attr_set = false;
        if (!attr_set) {
            cudaFuncSetAttribute(gemm_mma_kernel,
                                 cudaFuncAttributeMaxDynamicSharedMemorySize,
                                 SMEM_TOTAL);
            attr_set = true;
        }
        dim3 grid(D / 128, M_PAD / 128);  // (4, 391)
        gemm_mma_kernel<<<grid, 256, SMEM_TOTAL>>>(bias, out);
    }
}

// round 8
// speedup vs baseline: 2.6568x; 1.1727x over previous
#include <cuda_runtime.h>
#include <cuda_fp16.h>
#include <stdint.h>

// GCNConvDGL: out = segment_sum(x[src] -> dst) @ W + bias
// CSR aggregation + fp16 2-product split GEMM (A=hi+lo fp16, W=fp16 once).

#define N_NODES 50000
#define N_EDGES 800000
#define D       512
#define M_PAD   50048          // 391 * 128

// ---------------- scratch (static device globals) ----------------
__device__ __half  g_a_hi[(size_t)M_PAD * D];   // 51.2 MB
__device__ __half  g_a_lo[(size_t)M_PAD * D];   // 51.2 MB
__device__ __half  g_wt[(size_t)D * D];         // W^T fp16
__device__ int     g_cnt[N_NODES];
__device__ int     g_row[N_NODES + 1];
__device__ int     g_work[N_NODES];
__device__ int     g_csr[N_EDGES];

// ---------------- PTX helpers ----------------
__device__ __forceinline__ uint32_t smem_u32(const void* p) {
    uint32_t a;
    asm("{ .reg .u64 t; cvta.to.shared.u64 t, %1; cvt.u32.u64 %0, t; }"
        : "=r"(a) : "l"(p));
    return a;
}
__device__ __forceinline__ void cp_async16(uint32_t saddr, const void* gaddr) {
    asm volatile("cp.async.cg.shared.global [%0], [%1], 16;"
                 :: "r"(saddr), "l"(gaddr) : "memory");
}
__device__ __forceinline__ void cp_commit() {
    asm volatile("cp.async.commit_group;" ::: "memory");
}
template <int N> __device__ __forceinline__ void cp_wait() {
    asm volatile("cp.async.wait_group %0;" :: "n"(N) : "memory");
}
__device__ __forceinline__ void ldm_x4(uint32_t* r, uint32_t saddr) {
    asm volatile("ldmatrix.sync.aligned.m8n8.x4.shared.b16 {%0,%1,%2,%3}, [%4];"
                 : "=r"(r[0]), "=r"(r[1]), "=r"(r[2]), "=r"(r[3])
                 : "r"(saddr));
}
__device__ __forceinline__ void mma_fp16(float* c, const uint32_t* a,
                                         uint32_t b0, uint32_t b1) {
    asm volatile(
        "mma.sync.aligned.m16n8k16.row.col.f32.f16.f16.f32 "
        "{%0,%1,%2,%3}, {%4,%5,%6,%7}, {%8,%9}, {%0,%1,%2,%3};"
        : "+f"(c[0]), "+f"(c[1]), "+f"(c[2]), "+f"(c[3])
        : "r"(a[0]), "r"(a[1]), "r"(a[2]), "r"(a[3]), "r"(b0), "r"(b1));
}
__device__ __forceinline__ void st_cs_u2(void* p, uint2 v) {
    asm volatile("st.global.cs.v2.u32 [%0], {%1, %2};"
                 :: "l"(p), "r"(v.x), "r"(v.y) : "memory");
}

// ---------------------------------------------------------------------------
// CSR build
// ---------------------------------------------------------------------------
__global__ void zero_cnt_kernel() {
    int i = blockIdx.x * blockDim.x + threadIdx.x;
    if (i < N_NODES) g_cnt[i] = 0;
}

__global__ void __launch_bounds__(256) hist_kernel(const int* __restrict__ dst) {
    int e = blockIdx.x * blockDim.x + threadIdx.x;
    if (e < N_EDGES) atomicAdd(&g_cnt[dst[e]], 1);
}

__global__ void __launch_bounds__(1024) scan_kernel() {
    __shared__ int partial[1024];
    const int T = 1024;
    const int CHUNK = (N_NODES + T - 1) / T;   // 49
    int tid = threadIdx.x;
    int base = tid * CHUNK;

    int sum = 0;
    for (int i = 0; i < CHUNK; i++) {
        int idx = base + i;
        if (idx < N_NODES) sum += g_cnt[idx];
    }
    partial[tid] = sum;
    __syncthreads();

    for (int off = 1; off < T; off <<= 1) {
        int t = (tid >= off) ? partial[tid - off] : 0;
        __syncthreads();
        partial[tid] += t;
        __syncthreads();
    }

    int run = (tid == 0) ? 0 : partial[tid - 1];
    for (int i = 0; i < CHUNK; i++) {
        int idx = base + i;
        if (idx < N_NODES) {
            g_row[idx]  = run;
            g_work[idx] = run;
            run += g_cnt[idx];
        }
    }
    if (tid == T - 1) g_row[N_NODES] = run;
}

__global__ void __launch_bounds__(256) scatter_csr_kernel(
    const int* __restrict__ src, const int* __restrict__ dst)
{
    int e = blockIdx.x * blockDim.x + threadIdx.x;
    if (e < N_EDGES) {
        int pos = atomicAdd(&g_work[dst[e]], 1);
        g_csr[pos] = src[e];
    }
}

// ---------------------------------------------------------------------------
// Aggregation: one 128-thread block per node; unroll 4; fp16 hi/lo output.
// ---------------------------------------------------------------------------
__global__ void __launch_bounds__(128) agg_kernel(const float* __restrict__ x) {
    const int node = blockIdx.x;
    const int tid  = threadIdx.x;

    float4 acc = make_float4(0.f, 0.f, 0.f, 0.f);

    if (node < N_NODES) {
        const int s0 = g_row[node];
        const int s1 = g_row[node + 1];
        int e = s0;
        for (; e + 3 < s1; e += 4) {
            int sa = __ldg(&g_csr[e]);
            int sb = __ldg(&g_csr[e + 1]);
            int sc = __ldg(&g_csr[e + 2]);
            int sd = __ldg(&g_csr[e + 3]);
            float4 va = __ldg((const float4*)(x + (size_t)sa * D) + tid);
            float4 vb = __ldg((const float4*)(x + (size_t)sb * D) + tid);
            float4 vc = __ldg((const float4*)(x + (size_t)sc * D) + tid);
            float4 vd = __ldg((const float4*)(x + (size_t)sd * D) + tid);
            acc.x += va.x; acc.y += va.y; acc.z += va.z; acc.w += va.w;
            acc.x += vb.x; acc.y += vb.y; acc.z += vb.z; acc.w += vb.w;
            acc.x += vc.x; acc.y += vc.y; acc.z += vc.z; acc.w += vc.w;
            acc.x += vd.x; acc.y += vd.y; acc.z += vd.z; acc.w += vd.w;
        }
        for (; e < s1; e++) {
            int sa = __ldg(&g_csr[e]);
            float4 va = __ldg((const float4*)(x + (size_t)sa * D) + tid);
            acc.x += va.x; acc.y += va.y; acc.z += va.z; acc.w += va.w;
        }
    }

    float f[4] = {acc.x, acc.y, acc.z, acc.w};
    __half h[4], l[4];
    #pragma unroll
    for (int j = 0; j < 4; j++) {
        h[j] = __float2half_rn(f[j]);
        l[j] = __float2half_rn(f[j] - __half2float(h[j]));
    }
    size_t off = (size_t)node * D + tid * 4;
    st_cs_u2(g_a_hi + off, *(uint2*)h);
    st_cs_u2(g_a_lo + off, *(uint2*)l);
}

// ---------------------------------------------------------------------------
// Convert + transpose W fp32 [K,N] -> Wt fp16 [N,K]
// ---------------------------------------------------------------------------
__global__ void __launch_bounds__(256) convert_w_kernel(const float* __restrict__ W) {
    int idx = blockIdx.x * blockDim.x + threadIdx.x;
    if (idx >= D * D) return;
    int k = idx >> 9, n = idx & 511;
    g_wt[(size_t)n * D + k] = __float2half_rn(W[idx]);
}

// ---------------------------------------------------------------------------
// mma.sync fp16 2-product GEMM: C = (A_hi+A_lo) @ Wt^T + bias
// CTA 128x128, BK=32, 2-stage double buffer, 8 warps, warp tile 64x32.
// Stage holds 3 tiles: A_hi, A_lo, B. smem 60KB -> 2 CTAs/SM.
// ---------------------------------------------------------------------------
#define BK      32
#define KP      40                    // padded smem row stride (elements)
#define TILE_B  (128 * KP * 2)        // 10240 B per tile
#define STAGE_B (3 * TILE_B)          // Ah, Al, B = 30720 B
#define STAGES  2
#define SMEM_TOTAL (STAGES * STAGE_B) // 61440 B
#define NK      (D / BK)              // 16

__global__ void __launch_bounds__(256, 2) gemm_mma_kernel(
    const float* __restrict__ bias,
    float* __restrict__ C)
{
    extern __shared__ char smem[];
    const uint32_t smem_base = smem_u32(smem);
    const int tid  = threadIdx.x;
    const int wid  = tid >> 5;
    const int lane = tid & 31;
    const int wm   = wid >> 2;        // 0..1  (64 rows each)
    const int wn   = wid & 3;         // 0..3  (32 cols each)
    const int block_m = blockIdx.y * 128;
    const int block_n = blockIdx.x * 128;

    auto load_chunk = [&](int kt, int stage) {
        const int k0 = kt * BK;
        const uint32_t sb = smem_base + stage * STAGE_B;
        #pragma unroll
        for (int it = 0; it < 6; it++) {
            const int cid  = it * 256 + tid;      // 0..1535
            const int tile = cid >> 9;            // 0..2
            const int r    = (cid >> 2) & 127;
            const int c4   = cid & 3;
            const __half* g;
            if (tile == 0)      g = g_a_hi + (size_t)(block_m + r) * D;
            else if (tile == 1) g = g_a_lo + (size_t)(block_m + r) * D;
            else                g = g_wt   + (size_t)(block_n + r) * D;
            cp_async16(sb + tile * TILE_B + r * (KP * 2) + c4 * 16,
                       g + k0 + c4 * 8);
        }
        cp_commit();
    };

    float acc[4][4][4];
    #pragma unroll
    for (int i = 0; i < 4; i++)
        #pragma unroll
        for (int j = 0; j < 4; j++)
            #pragma unroll
            for (int e = 0; e < 4; e++)
                acc[i][j][e] = 0.f;

    load_chunk(0, 0);

    const uint32_t row_off = (uint32_t)(lane & 15) * (KP * 2);
    const uint32_t k_lane  = (uint32_t)((lane >> 4) << 4);   // 0 or 16 bytes

    for (int kt = 0; kt < NK; kt++) {
        if (kt + 1 < NK) {
            load_chunk(kt + 1, (kt + 1) & 1);
            cp_wait<1>();
        } else {
            cp_wait<0>();
        }
        __syncthreads();

        const uint32_t sb  = smem_base + (kt & 1) * STAGE_B;
        const uint32_t aH0 = sb + 0 * TILE_B + (wm * 64) * (KP * 2) + row_off;
        const uint32_t aL0 = sb + 1 * TILE_B + (wm * 64) * (KP * 2) + row_off;
        const uint32_t bF0 = sb + 2 * TILE_B + (wn * 32) * (KP * 2) + row_off;

        #pragma unroll
        for (int ks = 0; ks < 2; ks++) {
            const uint32_t koff = ks * 32 + k_lane;   // bytes
            uint32_t bF[2][4];
            #pragma unroll
            for (int np = 0; np < 2; np++)
                ldm_x4(bF[np], bF0 + np * 16 * (KP * 2) + koff);
            #pragma unroll
            for (int mt = 0; mt < 4; mt++) {
                uint32_t aH[4], aL[4];
                ldm_x4(aH, aH0 + mt * 16 * (KP * 2) + koff);
                ldm_x4(aL, aL0 + mt * 16 * (KP * 2) + koff);
                #pragma unroll
                for (int nt = 0; nt < 4; nt++) {
                    const int np = nt >> 1, sel = nt & 1;
                    mma_fp16(acc[mt][nt], aH, bF[np][sel], bF[np][sel + 2]);
                    mma_fp16(acc[mt][nt], aL, bF[np][sel], bF[np][sel + 2]);
                }
            }
        }
        __syncthreads();
    }

    #pragma unroll
    for (int nt = 0; nt < 4; nt++) {
        const int col = block_n + wn * 32 + nt * 8 + (lane & 3) * 2;
        const float2 bv = *(const float2*)(bias + col);
        #pragma unroll
        for (int mt = 0; mt < 4; mt++) {
            const int r0 = block_m + wm * 64 + mt * 16 + (lane >> 2);
            const int r1 = r0 + 8;
            if (r0 < N_NODES) {
                float2 o = make_float2(acc[mt][nt][0] + bv.x,
                                       acc[mt][nt][1] + bv.y);
                *(float2*)(C + (size_t)r0 * D + col) = o;
            }
            if (r1 < N_NODES) {
                float2 o = make_float2(acc[mt][nt][2] + bv.x,
                                       acc[mt][nt][3] + bv.y);
                *(float2*)(C + (size_t)r1 * D + col) = o;
            }
        }
    }
}

// ---------------------------------------------------------------------------
extern "C" void kernel_launch(void* const* d_in, const int* in_sizes, int n_in,
                              void* d_out, int out_size)
{
    const float* x      = (const float*)d_in[0];
    const float* weight = (const float*)d_in[1];
    const float* bias   = (const float*)d_in[2];
    const int*   src    = (const int*)d_in[3];
    const int*   dst    = (const int*)d_in[4];
    float*       out    = (float*)d_out;

    // CSR build
    zero_cnt_kernel<<<(N_NODES + 255) / 256, 256>>>();
    hist_kernel<<<(N_EDGES + 255) / 256, 256>>>(dst);
    scan_kernel<<<1, 1024>>>();
    scatter_csr_kernel<<<(N_EDGES + 255) / 256, 256>>>(src, dst);

    // Aggregate + fused fp16 hi/lo split
    agg_kernel<<<M_PAD, 128>>>(x);

    // Weight convert/transpose (fp16)
    convert_w_kernel<<<(D * D + 255) / 256, 256>>>(weight);

    // GEMM + bias
    {
        static bool attr_set = false;
        if (!attr_set) {
            cudaFuncSetAttribute(gemm_mma_kernel,
                                 cudaFuncAttributeMaxDynamicSharedMemorySize,
                                 SMEM_TOTAL);
            attr_set = true;
        }
        dim3 grid(D / 128, M_PAD / 128);  // (4, 391)
        gemm_mma_kernel<<<grid, 256, SMEM_TOTAL>>>(bias, out);
    }
}

// round 9
// speedup vs baseline: 2.8051x; 1.0558x over previous
#include <cuda_runtime.h>
#include <cuda_fp16.h>
#include <stdint.h>

// GCNConvDGL: out = segment_sum(x[src] -> dst) @ W + bias
// fp16 x-gather (L2-resident) + CSR aggregation + fp16 2-product GEMM.

#define N_NODES 50000
#define N_EDGES 800000
#define D       512
#define M_PAD   50048          // 391 * 128

// ---------------- scratch (static device globals) ----------------
__device__ __half  g_x16[(size_t)N_NODES * D];  // 51.2 MB, fp16 copy of x
__device__ __half  g_a_hi[(size_t)M_PAD * D];   // 51.2 MB
__device__ __half  g_a_lo[(size_t)M_PAD * D];   // 51.2 MB
__device__ __half  g_wt[(size_t)D * D];         // W^T fp16
__device__ int     g_cnt[N_NODES];
__device__ int     g_row[N_NODES + 1];
__device__ int     g_work[N_NODES];
__device__ int     g_csr[N_EDGES];

// ---------------- PTX helpers ----------------
__device__ __forceinline__ uint32_t smem_u32(const void* p) {
    uint32_t a;
    asm("{ .reg .u64 t; cvta.to.shared.u64 t, %1; cvt.u32.u64 %0, t; }"
        : "=r"(a) : "l"(p));
    return a;
}
__device__ __forceinline__ void cp_async16(uint32_t saddr, const void* gaddr) {
    asm volatile("cp.async.cg.shared.global [%0], [%1], 16;"
                 :: "r"(saddr), "l"(gaddr) : "memory");
}
__device__ __forceinline__ void cp_commit() {
    asm volatile("cp.async.commit_group;" ::: "memory");
}
template <int N> __device__ __forceinline__ void cp_wait() {
    asm volatile("cp.async.wait_group %0;" :: "n"(N) : "memory");
}
__device__ __forceinline__ void ldm_x4(uint32_t* r, uint32_t saddr) {
    asm volatile("ldmatrix.sync.aligned.m8n8.x4.shared.b16 {%0,%1,%2,%3}, [%4];"
                 : "=r"(r[0]), "=r"(r[1]), "=r"(r[2]), "=r"(r[3])
                 : "r"(saddr));
}
__device__ __forceinline__ void mma_fp16(float* c, const uint32_t* a,
                                         uint32_t b0, uint32_t b1) {
    asm volatile(
        "mma.sync.aligned.m16n8k16.row.col.f32.f16.f16.f32 "
        "{%0,%1,%2,%3}, {%4,%5,%6,%7}, {%8,%9}, {%0,%1,%2,%3};"
        : "+f"(c[0]), "+f"(c[1]), "+f"(c[2]), "+f"(c[3])
        : "r"(a[0]), "r"(a[1]), "r"(a[2]), "r"(a[3]), "r"(b0), "r"(b1));
}
__device__ __forceinline__ void st_cs_u2(void* p, uint2 v) {
    asm volatile("st.global.cs.v2.u32 [%0], {%1, %2};"
                 :: "l"(p), "r"(v.x), "r"(v.y) : "memory");
}

// ---------------------------------------------------------------------------
// CSR build
// ---------------------------------------------------------------------------
__global__ void zero_cnt_kernel() {
    int i = blockIdx.x * blockDim.x + threadIdx.x;
    if (i < N_NODES) g_cnt[i] = 0;
}

__global__ void __launch_bounds__(256) hist_kernel(const int* __restrict__ dst) {
    int e = blockIdx.x * blockDim.x + threadIdx.x;
    if (e < N_EDGES) atomicAdd(&g_cnt[dst[e]], 1);
}

__global__ void __launch_bounds__(1024) scan_kernel() {
    __shared__ int partial[1024];
    const int T = 1024;
    const int CHUNK = (N_NODES + T - 1) / T;   // 49
    int tid = threadIdx.x;
    int base = tid * CHUNK;

    int sum = 0;
    for (int i = 0; i < CHUNK; i++) {
        int idx = base + i;
        if (idx < N_NODES) sum += g_cnt[idx];
    }
    partial[tid] = sum;
    __syncthreads();

    for (int off = 1; off < T; off <<= 1) {
        int t = (tid >= off) ? partial[tid - off] : 0;
        __syncthreads();
        partial[tid] += t;
        __syncthreads();
    }

    int run = (tid == 0) ? 0 : partial[tid - 1];
    for (int i = 0; i < CHUNK; i++) {
        int idx = base + i;
        if (idx < N_NODES) {
            g_row[idx]  = run;
            g_work[idx] = run;
            run += g_cnt[idx];
        }
    }
    if (tid == T - 1) g_row[N_NODES] = run;
}

__global__ void __launch_bounds__(256) scatter_csr_kernel(
    const int* __restrict__ src, const int* __restrict__ dst)
{
    int e = blockIdx.x * blockDim.x + threadIdx.x;
    if (e < N_EDGES) {
        int pos = atomicAdd(&g_work[dst[e]], 1);
        g_csr[pos] = src[e];
    }
}

// ---------------------------------------------------------------------------
// Convert x fp32 -> fp16 (gather source; 50 MB, L2-resident)
// ---------------------------------------------------------------------------
__global__ void __launch_bounds__(256) convert_x_kernel(const float* __restrict__ x) {
    size_t i = ((size_t)blockIdx.x * blockDim.x + threadIdx.x) * 4;
    if (i >= (size_t)N_NODES * D) return;
    float4 v = *(const float4*)(x + i);
    __half h[4] = {__float2half_rn(v.x), __float2half_rn(v.y),
                   __float2half_rn(v.z), __float2half_rn(v.w)};
    *(uint2*)(g_x16 + i) = *(uint2*)h;
}

// ---------------------------------------------------------------------------
// Aggregation: one 128-thread block per node; gathers fp16 rows (1KB each),
// accumulates fp32, writes fp16 hi/lo split with streaming stores.
// ---------------------------------------------------------------------------
__global__ void __launch_bounds__(128) agg_kernel() {
    const int node = blockIdx.x;
    const int tid  = threadIdx.x;

    float4 acc = make_float4(0.f, 0.f, 0.f, 0.f);

    if (node < N_NODES) {
        const int s0 = g_row[node];
        const int s1 = g_row[node + 1];
        int e = s0;
        for (; e + 3 < s1; e += 4) {
            int sa = __ldg(&g_csr[e]);
            int sb = __ldg(&g_csr[e + 1]);
            int sc = __ldg(&g_csr[e + 2]);
            int sd = __ldg(&g_csr[e + 3]);
            __half2 va[2], vb[2], vc[2], vd[2];
            *(uint2*)va = __ldg((const uint2*)(g_x16 + (size_t)sa * D) + tid);
            *(uint2*)vb = __ldg((const uint2*)(g_x16 + (size_t)sb * D) + tid);
            *(uint2*)vc = __ldg((const uint2*)(g_x16 + (size_t)sc * D) + tid);
            *(uint2*)vd = __ldg((const uint2*)(g_x16 + (size_t)sd * D) + tid);
            float2 a0 = __half22float2(va[0]), a1 = __half22float2(va[1]);
            float2 b0 = __half22float2(vb[0]), b1 = __half22float2(vb[1]);
            float2 c0 = __half22float2(vc[0]), c1 = __half22float2(vc[1]);
            float2 d0 = __half22float2(vd[0]), d1 = __half22float2(vd[1]);
            acc.x += a0.x + b0.x + c0.x + d0.x;
            acc.y += a0.y + b0.y + c0.y + d0.y;
            acc.z += a1.x + b1.x + c1.x + d1.x;
            acc.w += a1.y + b1.y + c1.y + d1.y;
        }
        for (; e < s1; e++) {
            int sa = __ldg(&g_csr[e]);
            __half2 va[2];
            *(uint2*)va = __ldg((const uint2*)(g_x16 + (size_t)sa * D) + tid);
            float2 a0 = __half22float2(va[0]), a1 = __half22float2(va[1]);
            acc.x += a0.x; acc.y += a0.y; acc.z += a1.x; acc.w += a1.y;
        }
    }

    float f[4] = {acc.x, acc.y, acc.z, acc.w};
    __half h[4], l[4];
    #pragma unroll
    for (int j = 0; j < 4; j++) {
        h[j] = __float2half_rn(f[j]);
        l[j] = __float2half_rn(f[j] - __half2float(h[j]));
    }
    size_t off = (size_t)node * D + tid * 4;
    st_cs_u2(g_a_hi + off, *(uint2*)h);
    st_cs_u2(g_a_lo + off, *(uint2*)l);
}

// ---------------------------------------------------------------------------
// Convert + transpose W fp32 [K,N] -> Wt fp16 [N,K]
// ---------------------------------------------------------------------------
__global__ void __launch_bounds__(256) convert_w_kernel(const float* __restrict__ W) {
    int idx = blockIdx.x * blockDim.x + threadIdx.x;
    if (idx >= D * D) return;
    int k = idx >> 9, n = idx & 511;
    g_wt[(size_t)n * D + k] = __float2half_rn(W[idx]);
}

// ---------------------------------------------------------------------------
// mma.sync fp16 2-product GEMM: C = (A_hi+A_lo) @ Wt^T + bias
// CTA 128x128, BK=32, 2-stage double buffer, 8 warps, warp tile 64x32.
// ---------------------------------------------------------------------------
#define BK      32
#define KP      40                    // padded smem row stride (elements)
#define TILE_B  (128 * KP * 2)        // 10240 B per tile
#define STAGE_B (3 * TILE_B)          // Ah, Al, B = 30720 B
#define STAGES  2
#define SMEM_TOTAL (STAGES * STAGE_B) // 61440 B
#define NK      (D / BK)              // 16

__global__ void __launch_bounds__(256, 2) gemm_mma_kernel(
    const float* __restrict__ bias,
    float* __restrict__ C)
{
    extern __shared__ char smem[];
    const uint32_t smem_base = smem_u32(smem);
    const int tid  = threadIdx.x;
    const int wid  = tid >> 5;
    const int lane = tid & 31;
    const int wm   = wid >> 2;
    const int wn   = wid & 3;
    const int block_m = blockIdx.y * 128;
    const int block_n = blockIdx.x * 128;

    auto load_chunk = [&](int kt, int stage) {
        const int k0 = kt * BK;
        const uint32_t sb = smem_base + stage * STAGE_B;
        #pragma unroll
        for (int it = 0; it < 6; it++) {
            const int cid  = it * 256 + tid;      // 0..1535
            const int tile = cid >> 9;            // 0..2
            const int r    = (cid >> 2) & 127;
            const int c4   = cid & 3;
            const __half* g;
            if (tile == 0)      g = g_a_hi + (size_t)(block_m + r) * D;
            else if (tile == 1) g = g_a_lo + (size_t)(block_m + r) * D;
            else                g = g_wt   + (size_t)(block_n + r) * D;
            cp_async16(sb + tile * TILE_B + r * (KP * 2) + c4 * 16,
                       g + k0 + c4 * 8);
        }
        cp_commit();
    };

    float acc[4][4][4];
    #pragma unroll
    for (int i = 0; i < 4; i++)
        #pragma unroll
        for (int j = 0; j < 4; j++)
            #pragma unroll
            for (int e = 0; e < 4; e++)
                acc[i][j][e] = 0.f;

    load_chunk(0, 0);

    const uint32_t row_off = (uint32_t)(lane & 15) * (KP * 2);
    const uint32_t k_lane  = (uint32_t)((lane >> 4) << 4);

    for (int kt = 0; kt < NK; kt++) {
        if (kt + 1 < NK) {
            load_chunk(kt + 1, (kt + 1) & 1);
            cp_wait<1>();
        } else {
            cp_wait<0>();
        }
        __syncthreads();

        const uint32_t sb  = smem_base + (kt & 1) * STAGE_B;
        const uint32_t aH0 = sb + 0 * TILE_B + (wm * 64) * (KP * 2) + row_off;
        const uint32_t aL0 = sb + 1 * TILE_B + (wm * 64) * (KP * 2) + row_off;
        const uint32_t bF0 = sb + 2 * TILE_B + (wn * 32) * (KP * 2) + row_off;

        #pragma unroll
        for (int ks = 0; ks < 2; ks++) {
            const uint32_t koff = ks * 32 + k_lane;
            uint32_t bF[2][4];
            #pragma unroll
            for (int np = 0; np < 2; np++)
                ldm_x4(bF[np], bF0 + np * 16 * (KP * 2) + koff);
            #pragma unroll
            for (int mt = 0; mt < 4; mt++) {
                uint32_t aH[4], aL[4];
                ldm_x4(aH, aH0 + mt * 16 * (KP * 2) + koff);
                ldm_x4(aL, aL0 + mt * 16 * (KP * 2) + koff);
                #pragma unroll
                for (int nt = 0; nt < 4; nt++) {
                    const int np = nt >> 1, sel = nt & 1;
                    mma_fp16(acc[mt][nt], aH, bF[np][sel], bF[np][sel + 2]);
                    mma_fp16(acc[mt][nt], aL, bF[np][sel], bF[np][sel + 2]);
                }
            }
        }
        __syncthreads();
    }

    #pragma unroll
    for (int nt = 0; nt < 4; nt++) {
        const int col = block_n + wn * 32 + nt * 8 + (lane & 3) * 2;
        const float2 bv = *(const float2*)(bias + col);
        #pragma unroll
        for (int mt = 0; mt < 4; mt++) {
            const int r0 = block_m + wm * 64 + mt * 16 + (lane >> 2);
            const int r1 = r0 + 8;
            if (r0 < N_NODES) {
                float2 o = make_float2(acc[mt][nt][0] + bv.x,
                                       acc[mt][nt][1] + bv.y);
                *(float2*)(C + (size_t)r0 * D + col) = o;
            }
            if (r1 < N_NODES) {
                float2 o = make_float2(acc[mt][nt][2] + bv.x,
                                       acc[mt][nt][3] + bv.y);
                *(float2*)(C + (size_t)r1 * D + col) = o;
            }
        }
    }
}

// ---------------------------------------------------------------------------
extern "C" void kernel_launch(void* const* d_in, const int* in_sizes, int n_in,
                              void* d_out, int out_size)
{
    const float* x      = (const float*)d_in[0];
    const float* weight = (const float*)d_in[1];
    const float* bias   = (const float*)d_in[2];
    const int*   src    = (const int*)d_in[3];
    const int*   dst    = (const int*)d_in[4];
    float*       out    = (float*)d_out;

    // CSR build + x convert (independent, back-to-back)
    zero_cnt_kernel<<<(N_NODES + 255) / 256, 256>>>();
    hist_kernel<<<(N_EDGES + 255) / 256, 256>>>(dst);
    {
        size_t nthr = (size_t)N_NODES * D / 4;
        convert_x_kernel<<<(unsigned)((nthr + 255) / 256), 256>>>(x);
    }
    scan_kernel<<<1, 1024>>>();
    scatter_csr_kernel<<<(N_EDGES + 255) / 256, 256>>>(src, dst);

    // Aggregate from fp16 x + fused fp16 hi/lo split
    agg_kernel<<<M_PAD, 128>>>();

    // Weight convert/transpose (fp16)
    convert_w_kernel<<<(D * D + 255) / 256, 256>>>(weight);

    // GEMM + bias
    {
        static bool attr_set = false;
        if (!attr_set) {
            cudaFuncSetAttribute(gemm_mma_kernel,
                                 cudaFuncAttributeMaxDynamicSharedMemorySize,
                                 SMEM_TOTAL);
            attr_set = true;
        }
        dim3 grid(D / 128, M_PAD / 128);  // (4, 391)
        gemm_mma_kernel<<<grid, 256, SMEM_TOTAL>>>(bias, out);
    }
}

// round 10
// speedup vs baseline: 3.4309x; 1.2231x over previous
#include <cuda_runtime.h>
#include <cuda_fp16.h>
#include <stdint.h>

// GCNConvDGL: out = segment_sum(x[src] -> dst) @ W + bias
// fp16 x-gather + CSR aggregation (parallel scan) + fp16 2-product GEMM.

#define N_NODES 50000
#define N_EDGES 800000
#define D       512
#define M_PAD   50048          // 391 * 128
#define SCAN_NB 196            // ceil(50000 / 256)

// ---------------- scratch (static device globals) ----------------
__device__ __half  g_x16[(size_t)N_NODES * D];  // 51.2 MB, fp16 copy of x
__device__ __half  g_a_hi[(size_t)M_PAD * D];   // 51.2 MB
__device__ __half  g_a_lo[(size_t)M_PAD * D];   // 51.2 MB
__device__ __half  g_wt[(size_t)D * D];         // W^T fp16
__device__ int     g_cnt[N_NODES];
__device__ int     g_row[N_NODES + 1];
__device__ int     g_work[N_NODES];
__device__ int     g_csr[N_EDGES];
__device__ int     g_bsum[SCAN_NB];
__device__ int     g_boff[SCAN_NB];

// ---------------- PTX helpers ----------------
__device__ __forceinline__ uint32_t smem_u32(const void* p) {
    uint32_t a;
    asm("{ .reg .u64 t; cvta.to.shared.u64 t, %1; cvt.u32.u64 %0, t; }"
        : "=r"(a) : "l"(p));
    return a;
}
__device__ __forceinline__ void cp_async16(uint32_t saddr, const void* gaddr) {
    asm volatile("cp.async.cg.shared.global [%0], [%1], 16;"
                 :: "r"(saddr), "l"(gaddr) : "memory");
}
__device__ __forceinline__ void cp_commit() {
    asm volatile("cp.async.commit_group;" ::: "memory");
}
template <int N> __device__ __forceinline__ void cp_wait() {
    asm volatile("cp.async.wait_group %0;" :: "n"(N) : "memory");
}
__device__ __forceinline__ void ldm_x4(uint32_t* r, uint32_t saddr) {
    asm volatile("ldmatrix.sync.aligned.m8n8.x4.shared.b16 {%0,%1,%2,%3}, [%4];"
                 : "=r"(r[0]), "=r"(r[1]), "=r"(r[2]), "=r"(r[3])
                 : "r"(saddr));
}
__device__ __forceinline__ void mma_fp16(float* c, const uint32_t* a,
                                         uint32_t b0, uint32_t b1) {
    asm volatile(
        "mma.sync.aligned.m16n8k16.row.col.f32.f16.f16.f32 "
        "{%0,%1,%2,%3}, {%4,%5,%6,%7}, {%8,%9}, {%0,%1,%2,%3};"
        : "+f"(c[0]), "+f"(c[1]), "+f"(c[2]), "+f"(c[3])
        : "r"(a[0]), "r"(a[1]), "r"(a[2]), "r"(a[3]), "r"(b0), "r"(b1));
}
__device__ __forceinline__ void st_cs_u2(void* p, uint2 v) {
    asm volatile("st.global.cs.v2.u32 [%0], {%1, %2};"
                 :: "l"(p), "r"(v.x), "r"(v.y) : "memory");
}

// Warp-inclusive scan
__device__ __forceinline__ int warp_iscan(int v, int lane) {
    #pragma unroll
    for (int off = 1; off < 32; off <<= 1) {
        int t = __shfl_up_sync(0xFFFFFFFF, v, off);
        if (lane >= off) v += t;
    }
    return v;
}

// Block-exclusive scan of 256 values; returns exclusive prefix; *total gets
// block sum. Uses warp shuffles + one 8-entry smem stage.
__device__ __forceinline__ int block_escan256(int v, int tid, int* smem8, int* total) {
    const int lane = tid & 31, wid = tid >> 5;
    int inc = warp_iscan(v, lane);
    if (lane == 31) smem8[wid] = inc;
    __syncthreads();
    if (wid == 0) {
        int ws = (lane < 8) ? smem8[lane] : 0;
        ws = warp_iscan(ws, lane);
        if (lane < 8) smem8[lane] = ws;
    }
    __syncthreads();
    int woff = (wid > 0) ? smem8[wid - 1] : 0;
    *total = smem8[7];
    return inc - v + woff;
}

// ---------------------------------------------------------------------------
// CSR build
// ---------------------------------------------------------------------------
__global__ void zero_cnt_kernel() {
    int i = blockIdx.x * blockDim.x + threadIdx.x;
    if (i < N_NODES) g_cnt[i] = 0;
}

__global__ void __launch_bounds__(256) hist_kernel(const int* __restrict__ dst) {
    int e = blockIdx.x * blockDim.x + threadIdx.x;
    if (e < N_EDGES) atomicAdd(&g_cnt[dst[e]], 1);
}

// scan1: per-block exclusive scan; partials to g_row, block totals to g_bsum
__global__ void __launch_bounds__(256) scan1_kernel() {
    __shared__ int smem8[8];
    int tid = threadIdx.x;
    int i = blockIdx.x * 256 + tid;
    int v = (i < N_NODES) ? g_cnt[i] : 0;
    int total;
    int excl = block_escan256(v, tid, smem8, &total);
    if (i < N_NODES) g_row[i] = excl;
    if (tid == 0) g_bsum[blockIdx.x] = total;
}

// scan2: single block scans the SCAN_NB block sums -> g_boff (exclusive)
__global__ void __launch_bounds__(256) scan2_kernel() {
    __shared__ int smem8[8];
    int tid = threadIdx.x;
    int v = (tid < SCAN_NB) ? g_bsum[tid] : 0;
    int total;
    int excl = block_escan256(v, tid, smem8, &total);
    if (tid < SCAN_NB) g_boff[tid] = excl;
}

// scan3: add block offsets; finalize g_row / g_work
__global__ void __launch_bounds__(256) scan3_kernel() {
    int i = blockIdx.x * 256 + threadIdx.x;
    if (i < N_NODES) {
        int r = g_row[i] + g_boff[i >> 8];
        g_row[i]  = r;
        g_work[i] = r;
    }
    if (i == 0) g_row[N_NODES] = N_EDGES;
}

__global__ void __launch_bounds__(256) scatter_csr_kernel(
    const int* __restrict__ src, const int* __restrict__ dst)
{
    int e = blockIdx.x * blockDim.x + threadIdx.x;
    if (e < N_EDGES) {
        int pos = atomicAdd(&g_work[dst[e]], 1);
        g_csr[pos] = src[e];
    }
}

// ---------------------------------------------------------------------------
// Convert x fp32 -> fp16 (gather source; 50 MB, mostly L2-resident)
// ---------------------------------------------------------------------------
__global__ void __launch_bounds__(256) convert_x_kernel(const float* __restrict__ x) {
    size_t i = ((size_t)blockIdx.x * blockDim.x + threadIdx.x) * 4;
    if (i >= (size_t)N_NODES * D) return;
    float4 v = *(const float4*)(x + i);
    __half h[4] = {__float2half_rn(v.x), __float2half_rn(v.y),
                   __float2half_rn(v.z), __float2half_rn(v.w)};
    *(uint2*)(g_x16 + i) = *(uint2*)h;
}

// ---------------------------------------------------------------------------
// Aggregation: one 128-thread block per node; fp16 gathers, fp32 accumulate,
// fp16 hi/lo split output with streaming stores.
// ---------------------------------------------------------------------------
__global__ void __launch_bounds__(128) agg_kernel() {
    const int node = blockIdx.x;
    const int tid  = threadIdx.x;

    float4 acc = make_float4(0.f, 0.f, 0.f, 0.f);

    if (node < N_NODES) {
        const int s0 = g_row[node];
        const int s1 = g_row[node + 1];
        int e = s0;
        for (; e + 3 < s1; e += 4) {
            int sa = __ldg(&g_csr[e]);
            int sb = __ldg(&g_csr[e + 1]);
            int sc = __ldg(&g_csr[e + 2]);
            int sd = __ldg(&g_csr[e + 3]);
            __half2 va[2], vb[2], vc[2], vd[2];
            *(uint2*)va = __ldg((const uint2*)(g_x16 + (size_t)sa * D) + tid);
            *(uint2*)vb = __ldg((const uint2*)(g_x16 + (size_t)sb * D) + tid);
            *(uint2*)vc = __ldg((const uint2*)(g_x16 + (size_t)sc * D) + tid);
            *(uint2*)vd = __ldg((const uint2*)(g_x16 + (size_t)sd * D) + tid);
            float2 a0 = __half22float2(va[0]), a1 = __half22float2(va[1]);
            float2 b0 = __half22float2(vb[0]), b1 = __half22float2(vb[1]);
            float2 c0 = __half22float2(vc[0]), c1 = __half22float2(vc[1]);
            float2 d0 = __half22float2(vd[0]), d1 = __half22float2(vd[1]);
            acc.x += a0.x + b0.x + c0.x + d0.x;
            acc.y += a0.y + b0.y + c0.y + d0.y;
            acc.z += a1.x + b1.x + c1.x + d1.x;
            acc.w += a1.y + b1.y + c1.y + d1.y;
        }
        for (; e < s1; e++) {
            int sa = __ldg(&g_csr[e]);
            __half2 va[2];
            *(uint2*)va = __ldg((const uint2*)(g_x16 + (size_t)sa * D) + tid);
            float2 a0 = __half22float2(va[0]), a1 = __half22float2(va[1]);
            acc.x += a0.x; acc.y += a0.y; acc.z += a1.x; acc.w += a1.y;
        }
    }

    float f[4] = {acc.x, acc.y, acc.z, acc.w};
    __half h[4], l[4];
    #pragma unroll
    for (int j = 0; j < 4; j++) {
        h[j] = __float2half_rn(f[j]);
        l[j] = __float2half_rn(f[j] - __half2float(h[j]));
    }
    size_t off = (size_t)node * D + tid * 4;
    st_cs_u2(g_a_hi + off, *(uint2*)h);
    st_cs_u2(g_a_lo + off, *(uint2*)l);
}

// ---------------------------------------------------------------------------
// Convert + transpose W fp32 [K,N] -> Wt fp16 [N,K]
// ---------------------------------------------------------------------------
__global__ void __launch_bounds__(256) convert_w_kernel(const float* __restrict__ W) {
    int idx = blockIdx.x * blockDim.x + threadIdx.x;
    if (idx >= D * D) return;
    int k = idx >> 9, n = idx & 511;
    g_wt[(size_t)n * D + k] = __float2half_rn(W[idx]);
}

// ---------------------------------------------------------------------------
// mma.sync fp16 2-product GEMM: C = (A_hi+A_lo) @ Wt^T + bias
// CTA 128x128, BK=32, 2-stage double buffer, 8 warps, warp tile 64x32.
// ---------------------------------------------------------------------------
#define BK      32
#define KP      40                    // padded smem row stride (elements)
#define TILE_B  (128 * KP * 2)        // 10240 B per tile
#define STAGE_B (3 * TILE_B)          // Ah, Al, B = 30720 B
#define STAGES  2
#define SMEM_TOTAL (STAGES * STAGE_B) // 61440 B
#define NK      (D / BK)              // 16

__global__ void __launch_bounds__(256, 2) gemm_mma_kernel(
    const float* __restrict__ bias,
    float* __restrict__ C)
{
    extern __shared__ char smem[];
    const uint32_t smem_base = smem_u32(smem);
    const int tid  = threadIdx.x;
    const int wid  = tid >> 5;
    const int lane = tid & 31;
    const int wm   = wid >> 2;
    const int wn   = wid & 3;
    const int block_m = blockIdx.y * 128;
    const int block_n = blockIdx.x * 128;

    auto load_chunk = [&](int kt, int stage) {
        const int k0 = kt * BK;
        const uint32_t sb = smem_base + stage * STAGE_B;
        #pragma unroll
        for (int it = 0; it < 6; it++) {
            const int cid  = it * 256 + tid;      // 0..1535
            const int tile = cid >> 9;            // 0..2
            const int r    = (cid >> 2) & 127;
            const int c4   = cid & 3;
            const __half* g;
            if (tile == 0)      g = g_a_hi + (size_t)(block_m + r) * D;
            else if (tile == 1) g = g_a_lo + (size_t)(block_m + r) * D;
            else                g = g_wt   + (size_t)(block_n + r) * D;
            cp_async16(sb + tile * TILE_B + r * (KP * 2) + c4 * 16,
                       g + k0 + c4 * 8);
        }
        cp_commit();
    };

    float acc[4][4][4];
    #pragma unroll
    for (int i = 0; i < 4; i++)
        #pragma unroll
        for (int j = 0; j < 4; j++)
            #pragma unroll
            for (int e = 0; e < 4; e++)
                acc[i][j][e] = 0.f;

    load_chunk(0, 0);

    const uint32_t row_off = (uint32_t)(lane & 15) * (KP * 2);
    const uint32_t k_lane  = (uint32_t)((lane >> 4) << 4);

    for (int kt = 0; kt < NK; kt++) {
        if (kt + 1 < NK) {
            load_chunk(kt + 1, (kt + 1) & 1);
            cp_wait<1>();
        } else {
            cp_wait<0>();
        }
        __syncthreads();

        const uint32_t sb  = smem_base + (kt & 1) * STAGE_B;
        const uint32_t aH0 = sb + 0 * TILE_B + (wm * 64) * (KP * 2) + row_off;
        const uint32_t aL0 = sb + 1 * TILE_B + (wm * 64) * (KP * 2) + row_off;
        const uint32_t bF0 = sb + 2 * TILE_B + (wn * 32) * (KP * 2) + row_off;

        #pragma unroll
        for (int ks = 0; ks < 2; ks++) {
            const uint32_t koff = ks * 32 + k_lane;
            uint32_t bF[2][4];
            #pragma unroll
            for (int np = 0; np < 2; np++)
                ldm_x4(bF[np], bF0 + np * 16 * (KP * 2) + koff);
            #pragma unroll
            for (int mt = 0; mt < 4; mt++) {
                uint32_t aH[4], aL[4];
                ldm_x4(aH, aH0 + mt * 16 * (KP * 2) + koff);
                ldm_x4(aL, aL0 + mt * 16 * (KP * 2) + koff);
                #pragma unroll
                for (int nt = 0; nt < 4; nt++) {
                    const int np = nt >> 1, sel = nt & 1;
                    mma_fp16(acc[mt][nt], aH, bF[np][sel], bF[np][sel + 2]);
                    mma_fp16(acc[mt][nt], aL, bF[np][sel], bF[np][sel + 2]);
                }
            }
        }
        __syncthreads();
    }

    #pragma unroll
    for (int nt = 0; nt < 4; nt++) {
        const int col = block_n + wn * 32 + nt * 8 + (lane & 3) * 2;
        const float2 bv = *(const float2*)(bias + col);
        #pragma unroll
        for (int mt = 0; mt < 4; mt++) {
            const int r0 = block_m + wm * 64 + mt * 16 + (lane >> 2);
            const int r1 = r0 + 8;
            if (r0 < N_NODES) {
                float2 o = make_float2(acc[mt][nt][0] + bv.x,
                                       acc[mt][nt][1] + bv.y);
                *(float2*)(C + (size_t)r0 * D + col) = o;
            }
            if (r1 < N_NODES) {
                float2 o = make_float2(acc[mt][nt][2] + bv.x,
                                       acc[mt][nt][3] + bv.y);
                *(float2*)(C + (size_t)r1 * D + col) = o;
            }
        }
    }
}

// ---------------------------------------------------------------------------
extern "C" void kernel_launch(void* const* d_in, const int* in_sizes, int n_in,
                              void* d_out, int out_size)
{
    const float* x      = (const float*)d_in[0];
    const float* weight = (const float*)d_in[1];
    const float* bias   = (const float*)d_in[2];
    const int*   src    = (const int*)d_in[3];
    const int*   dst    = (const int*)d_in[4];
    float*       out    = (float*)d_out;

    // CSR build (parallel scan) + x convert
    zero_cnt_kernel<<<(N_NODES + 255) / 256, 256>>>();
    hist_kernel<<<(N_EDGES + 255) / 256, 256>>>(dst);
    {
        size_t nthr = (size_t)N_NODES * D / 4;
        convert_x_kernel<<<(unsigned)((nthr + 255) / 256), 256>>>(x);
    }
    scan1_kernel<<<SCAN_NB, 256>>>();
    scan2_kernel<<<1, 256>>>();
    scan3_kernel<<<SCAN_NB, 256>>>();
    scatter_csr_kernel<<<(N_EDGES + 255) / 256, 256>>>(src, dst);

    // Aggregate from fp16 x + fused fp16 hi/lo split
    agg_kernel<<<M_PAD, 128>>>();

    // Weight convert/transpose (fp16)
    convert_w_kernel<<<(D * D + 255) / 256, 256>>>(weight);

    // GEMM + bias
    {
        static bool attr_set = false;
        if (!attr_set) {
            cudaFuncSetAttribute(gemm_mma_kernel,
                                 cudaFuncAttributeMaxDynamicSharedMemorySize,
                                 SMEM_TOTAL);
            attr_set = true;
        }
        dim3 grid(D / 128, M_PAD / 128);  // (4, 391)
        gemm_mma_kernel<<<grid, 256, SMEM_TOTAL>>>(bias, out);
    }
}

// round 11
// speedup vs baseline: 4.5875x; 1.3371x over previous
#include <cuda_runtime.h>
#include <cuda_fp16.h>
#include <stdint.h>

// GCNConvDGL: out = segment_sum(x[src] -> dst) @ W + bias
// fp16 x-gather + CSR aggregation (parallel scan) + single-product fp16 GEMM.

#define N_NODES 50000
#define N_EDGES 800000
#define D       512
#define M_PAD   50048          // 391 * 128
#define SCAN_NB 196            // ceil(50000 / 256)

// ---------------- scratch (static device globals) ----------------
__device__ __half  g_x16[(size_t)N_NODES * D];  // 51.2 MB, fp16 copy of x
__device__ __half  g_a[(size_t)M_PAD * D];      // 51.2 MB, fp16 agg
__device__ __half  g_wt[(size_t)D * D];         // W^T fp16
__device__ int     g_cnt[N_NODES];
__device__ int     g_row[N_NODES + 1];
__device__ int     g_work[N_NODES];
__device__ int     g_csr[N_EDGES];
__device__ int     g_bsum[SCAN_NB];
__device__ int     g_boff[SCAN_NB];

// ---------------- PTX helpers ----------------
__device__ __forceinline__ uint32_t smem_u32(const void* p) {
    uint32_t a;
    asm("{ .reg .u64 t; cvta.to.shared.u64 t, %1; cvt.u32.u64 %0, t; }"
        : "=r"(a) : "l"(p));
    return a;
}
__device__ __forceinline__ void cp_async16(uint32_t saddr, const void* gaddr) {
    asm volatile("cp.async.cg.shared.global [%0], [%1], 16;"
                 :: "r"(saddr), "l"(gaddr) : "memory");
}
__device__ __forceinline__ void cp_commit() {
    asm volatile("cp.async.commit_group;" ::: "memory");
}
template <int N> __device__ __forceinline__ void cp_wait() {
    asm volatile("cp.async.wait_group %0;" :: "n"(N) : "memory");
}
__device__ __forceinline__ void ldm_x4(uint32_t* r, uint32_t saddr) {
    asm volatile("ldmatrix.sync.aligned.m8n8.x4.shared.b16 {%0,%1,%2,%3}, [%4];"
                 : "=r"(r[0]), "=r"(r[1]), "=r"(r[2]), "=r"(r[3])
                 : "r"(saddr));
}
__device__ __forceinline__ void mma_fp16(float* c, const uint32_t* a,
                                         uint32_t b0, uint32_t b1) {
    asm volatile(
        "mma.sync.aligned.m16n8k16.row.col.f32.f16.f16.f32 "
        "{%0,%1,%2,%3}, {%4,%5,%6,%7}, {%8,%9}, {%0,%1,%2,%3};"
        : "+f"(c[0]), "+f"(c[1]), "+f"(c[2]), "+f"(c[3])
        : "r"(a[0]), "r"(a[1]), "r"(a[2]), "r"(a[3]), "r"(b0), "r"(b1));
}
__device__ __forceinline__ void st_cs_u2(void* p, uint2 v) {
    asm volatile("st.global.cs.v2.u32 [%0], {%1, %2};"
                 :: "l"(p), "r"(v.x), "r"(v.y) : "memory");
}

// Warp-inclusive scan
__device__ __forceinline__ int warp_iscan(int v, int lane) {
    #pragma unroll
    for (int off = 1; off < 32; off <<= 1) {
        int t = __shfl_up_sync(0xFFFFFFFF, v, off);
        if (lane >= off) v += t;
    }
    return v;
}

__device__ __forceinline__ int block_escan256(int v, int tid, int* smem8, int* total) {
    const int lane = tid & 31, wid = tid >> 5;
    int inc = warp_iscan(v, lane);
    if (lane == 31) smem8[wid] = inc;
    __syncthreads();
    if (wid == 0) {
        int ws = (lane < 8) ? smem8[lane] : 0;
        ws = warp_iscan(ws, lane);
        if (lane < 8) smem8[lane] = ws;
    }
    __syncthreads();
    int woff = (wid > 0) ? smem8[wid - 1] : 0;
    *total = smem8[7];
    return inc - v + woff;
}

// ---------------------------------------------------------------------------
// CSR build
// ---------------------------------------------------------------------------
__global__ void zero_cnt_kernel() {
    int i = blockIdx.x * blockDim.x + threadIdx.x;
    if (i < N_NODES) g_cnt[i] = 0;
}

__global__ void __launch_bounds__(256) hist_kernel(const int* __restrict__ dst) {
    int e = blockIdx.x * blockDim.x + threadIdx.x;
    if (e < N_EDGES) atomicAdd(&g_cnt[dst[e]], 1);
}

__global__ void __launch_bounds__(256) scan1_kernel() {
    __shared__ int smem8[8];
    int tid = threadIdx.x;
    int i = blockIdx.x * 256 + tid;
    int v = (i < N_NODES) ? g_cnt[i] : 0;
    int total;
    int excl = block_escan256(v, tid, smem8, &total);
    if (i < N_NODES) g_row[i] = excl;
    if (tid == 0) g_bsum[blockIdx.x] = total;
}

__global__ void __launch_bounds__(256) scan2_kernel() {
    __shared__ int smem8[8];
    int tid = threadIdx.x;
    int v = (tid < SCAN_NB) ? g_bsum[tid] : 0;
    int total;
    int excl = block_escan256(v, tid, smem8, &total);
    if (tid < SCAN_NB) g_boff[tid] = excl;
}

__global__ void __launch_bounds__(256) scan3_kernel() {
    int i = blockIdx.x * 256 + threadIdx.x;
    if (i < N_NODES) {
        int r = g_row[i] + g_boff[i >> 8];
        g_row[i]  = r;
        g_work[i] = r;
    }
    if (i == 0) g_row[N_NODES] = N_EDGES;
}

__global__ void __launch_bounds__(256) scatter_csr_kernel(
    const int* __restrict__ src, const int* __restrict__ dst)
{
    int e = blockIdx.x * blockDim.x + threadIdx.x;
    if (e < N_EDGES) {
        int pos = atomicAdd(&g_work[dst[e]], 1);
        g_csr[pos] = src[e];
    }
}

// ---------------------------------------------------------------------------
// Convert x fp32 -> fp16 (gather source; 50 MB, mostly L2-resident)
// ---------------------------------------------------------------------------
__global__ void __launch_bounds__(256) convert_x_kernel(const float* __restrict__ x) {
    size_t i = ((size_t)blockIdx.x * blockDim.x + threadIdx.x) * 4;
    if (i >= (size_t)N_NODES * D) return;
    float4 v = *(const float4*)(x + i);
    __half h[4] = {__float2half_rn(v.x), __float2half_rn(v.y),
                   __float2half_rn(v.z), __float2half_rn(v.w)};
    *(uint2*)(g_x16 + i) = *(uint2*)h;
}

// ---------------------------------------------------------------------------
// Aggregation: one 128-thread block per node; fp16 gathers, fp32 accumulate,
// single fp16 output row with streaming stores.
// ---------------------------------------------------------------------------
__global__ void __launch_bounds__(128) agg_kernel() {
    const int node = blockIdx.x;
    const int tid  = threadIdx.x;

    float4 acc = make_float4(0.f, 0.f, 0.f, 0.f);

    if (node < N_NODES) {
        const int s0 = g_row[node];
        const int s1 = g_row[node + 1];
        int e = s0;
        for (; e + 3 < s1; e += 4) {
            int sa = __ldg(&g_csr[e]);
            int sb = __ldg(&g_csr[e + 1]);
            int sc = __ldg(&g_csr[e + 2]);
            int sd = __ldg(&g_csr[e + 3]);
            __half2 va[2], vb[2], vc[2], vd[2];
            *(uint2*)va = __ldg((const uint2*)(g_x16 + (size_t)sa * D) + tid);
            *(uint2*)vb = __ldg((const uint2*)(g_x16 + (size_t)sb * D) + tid);
            *(uint2*)vc = __ldg((const uint2*)(g_x16 + (size_t)sc * D) + tid);
            *(uint2*)vd = __ldg((const uint2*)(g_x16 + (size_t)sd * D) + tid);
            float2 a0 = __half22float2(va[0]), a1 = __half22float2(va[1]);
            float2 b0 = __half22float2(vb[0]), b1 = __half22float2(vb[1]);
            float2 c0 = __half22float2(vc[0]), c1 = __half22float2(vc[1]);
            float2 d0 = __half22float2(vd[0]), d1 = __half22float2(vd[1]);
            acc.x += a0.x + b0.x + c0.x + d0.x;
            acc.y += a0.y + b0.y + c0.y + d0.y;
            acc.z += a1.x + b1.x + c1.x + d1.x;
            acc.w += a1.y + b1.y + c1.y + d1.y;
        }
        for (; e < s1; e++) {
            int sa = __ldg(&g_csr[e]);
            __half2 va[2];
            *(uint2*)va = __ldg((const uint2*)(g_x16 + (size_t)sa * D) + tid);
            float2 a0 = __half22float2(va[0]), a1 = __half22float2(va[1]);
            acc.x += a0.x; acc.y += a0.y; acc.z += a1.x; acc.w += a1.y;
        }
    }

    __half h[4] = {__float2half_rn(acc.x), __float2half_rn(acc.y),
                   __float2half_rn(acc.z), __float2half_rn(acc.w)};
    st_cs_u2(g_a + (size_t)node * D + tid * 4, *(uint2*)h);
}

// ---------------------------------------------------------------------------
// Convert + transpose W fp32 [K,N] -> Wt fp16 [N,K]
// ---------------------------------------------------------------------------
__global__ void __launch_bounds__(256) convert_w_kernel(const float* __restrict__ W) {
    int idx = blockIdx.x * blockDim.x + threadIdx.x;
    if (idx >= D * D) return;
    int k = idx >> 9, n = idx & 511;
    g_wt[(size_t)n * D + k] = __float2half_rn(W[idx]);
}

// ---------------------------------------------------------------------------
// mma.sync fp16 single-product GEMM: C = A @ Wt^T + bias
// CTA 128x128, BK=32, 2-stage double buffer, 8 warps, warp tile 64x32.
// Stage holds 2 tiles (A, B) = 20480 B; smem total 40 KB.
// ---------------------------------------------------------------------------
#define BK      32
#define KP      40                    // padded smem row stride (elements)
#define TILE_B  (128 * KP * 2)        // 10240 B per tile
#define STAGE_B (2 * TILE_B)          // A, B = 20480 B
#define STAGES  2
#define SMEM_TOTAL (STAGES * STAGE_B) // 40960 B
#define NK      (D / BK)              // 16

__global__ void __launch_bounds__(256, 2) gemm_mma_kernel(
    const float* __restrict__ bias,
    float* __restrict__ C)
{
    extern __shared__ char smem[];
    const uint32_t smem_base = smem_u32(smem);
    const int tid  = threadIdx.x;
    const int wid  = tid >> 5;
    const int lane = tid & 31;
    const int wm   = wid >> 2;
    const int wn   = wid & 3;
    const int block_m = blockIdx.y * 128;
    const int block_n = blockIdx.x * 128;

    auto load_chunk = [&](int kt, int stage) {
        const int k0 = kt * BK;
        const uint32_t sb = smem_base + stage * STAGE_B;
        #pragma unroll
        for (int it = 0; it < 4; it++) {
            const int cid  = it * 256 + tid;      // 0..1023
            const int tile = cid >> 9;            // 0..1
            const int r    = (cid >> 2) & 127;
            const int c4   = cid & 3;
            const __half* g;
            if (tile == 0) g = g_a  + (size_t)(block_m + r) * D;
            else           g = g_wt + (size_t)(block_n + r) * D;
            cp_async16(sb + tile * TILE_B + r * (KP * 2) + c4 * 16,
                       g + k0 + c4 * 8);
        }
        cp_commit();
    };

    float acc[4][4][4];
    #pragma unroll
    for (int i = 0; i < 4; i++)
        #pragma unroll
        for (int j = 0; j < 4; j++)
            #pragma unroll
            for (int e = 0; e < 4; e++)
                acc[i][j][e] = 0.f;

    load_chunk(0, 0);

    const uint32_t row_off = (uint32_t)(lane & 15) * (KP * 2);
    const uint32_t k_lane  = (uint32_t)((lane >> 4) << 4);

    for (int kt = 0; kt < NK; kt++) {
        if (kt + 1 < NK) {
            load_chunk(kt + 1, (kt + 1) & 1);
            cp_wait<1>();
        } else {
            cp_wait<0>();
        }
        __syncthreads();

        const uint32_t sb  = smem_base + (kt & 1) * STAGE_B;
        const uint32_t aF0 = sb + 0 * TILE_B + (wm * 64) * (KP * 2) + row_off;
        const uint32_t bF0 = sb + 1 * TILE_B + (wn * 32) * (KP * 2) + row_off;

        #pragma unroll
        for (int ks = 0; ks < 2; ks++) {
            const uint32_t koff = ks * 32 + k_lane;
            uint32_t bF[2][4];
            #pragma unroll
            for (int np = 0; np < 2; np++)
                ldm_x4(bF[np], bF0 + np * 16 * (KP * 2) + koff);
            #pragma unroll
            for (int mt = 0; mt < 4; mt++) {
                uint32_t aF[4];
                ldm_x4(aF, aF0 + mt * 16 * (KP * 2) + koff);
                #pragma unroll
                for (int nt = 0; nt < 4; nt++) {
                    const int np = nt >> 1, sel = nt & 1;
                    mma_fp16(acc[mt][nt], aF, bF[np][sel], bF[np][sel + 2]);
                }
            }
        }
        __syncthreads();
    }

    #pragma unroll
    for (int nt = 0; nt < 4; nt++) {
        const int col = block_n + wn * 32 + nt * 8 + (lane & 3) * 2;
        const float2 bv = *(const float2*)(bias + col);
        #pragma unroll
        for (int mt = 0; mt < 4; mt++) {
            const int r0 = block_m + wm * 64 + mt * 16 + (lane >> 2);
            const int r1 = r0 + 8;
            if (r0 < N_NODES) {
                float2 o = make_float2(acc[mt][nt][0] + bv.x,
                                       acc[mt][nt][1] + bv.y);
                *(float2*)(C + (size_t)r0 * D + col) = o;
            }
            if (r1 < N_NODES) {
                float2 o = make_float2(acc[mt][nt][2] + bv.x,
                                       acc[mt][nt][3] + bv.y);
                *(float2*)(C + (size_t)r1 * D + col) = o;
            }
        }
    }
}

// ---------------------------------------------------------------------------
extern "C" void kernel_launch(void* const* d_in, const int* in_sizes, int n_in,
                              void* d_out, int out_size)
{
    const float* x      = (const float*)d_in[0];
    const float* weight = (const float*)d_in[1];
    const float* bias   = (const float*)d_in[2];
    const int*   src    = (const int*)d_in[3];
    const int*   dst    = (const int*)d_in[4];
    float*       out    = (float*)d_out;

    // CSR build (parallel scan) + x convert
    zero_cnt_kernel<<<(N_NODES + 255) / 256, 256>>>();
    hist_kernel<<<(N_EDGES + 255) / 256, 256>>>(dst);
    {
        size_t nthr = (size_t)N_NODES * D / 4;
        convert_x_kernel<<<(unsigned)((nthr + 255) / 256), 256>>>(x);
    }
    scan1_kernel<<<SCAN_NB, 256>>>();
    scan2_kernel<<<1, 256>>>();
    scan3_kernel<<<SCAN_NB, 256>>>();
    scatter_csr_kernel<<<(N_EDGES + 255) / 256, 256>>>(src, dst);

    // Aggregate from fp16 x -> single fp16 plane
    agg_kernel<<<M_PAD, 128>>>();

    // Weight convert/transpose (fp16)
    convert_w_kernel<<<(D * D + 255) / 256, 256>>>(weight);

    // GEMM + bias
    {
        static bool attr_set = false;
        if (!attr_set) {
            cudaFuncSetAttribute(gemm_mma_kernel,
                                 cudaFuncAttributeMaxDynamicSharedMemorySize,
                                 SMEM_TOTAL);
            attr_set = true;
        }
        dim3 grid(D / 128, M_PAD / 128);  // (4, 391)
        gemm_mma_kernel<<<grid, 256, SMEM_TOTAL>>>(bias, out);
    }
}

// round 12
// speedup vs baseline: 4.6407x; 1.0116x over previous
#include <cuda_runtime.h>
#include <cuda_fp16.h>
#include <stdint.h>

// GCNConvDGL: out = segment_sum(x[src] -> dst) @ W + bias
// fp16 x-gather + CSR aggregation (parallel scan) + single-product fp16 GEMM.

#define N_NODES 50000
#define N_EDGES 800000
#define D       512
#define M_PAD   50048          // 391 * 128
#define SCAN_NB 196            // ceil(50000 / 256)

// ---------------- scratch (static device globals) ----------------
__device__ __half  g_x16[(size_t)N_NODES * D];  // 51.2 MB, fp16 copy of x
__device__ __half  g_a[(size_t)M_PAD * D];      // 51.2 MB, fp16 agg
__device__ __half  g_wt[(size_t)D * D];         // W^T fp16
__device__ int     g_cnt[N_NODES];
__device__ int     g_row[N_NODES + 1];
__device__ int     g_work[N_NODES];
__device__ int     g_csr[N_EDGES];
__device__ int     g_bsum[SCAN_NB];
__device__ int     g_boff[SCAN_NB];

// ---------------- PTX helpers ----------------
__device__ __forceinline__ uint32_t smem_u32(const void* p) {
    uint32_t a;
    asm("{ .reg .u64 t; cvta.to.shared.u64 t, %1; cvt.u32.u64 %0, t; }"
        : "=r"(a) : "l"(p));
    return a;
}
__device__ __forceinline__ void cp_async16(uint32_t saddr, const void* gaddr) {
    asm volatile("cp.async.cg.shared.global [%0], [%1], 16;"
                 :: "r"(saddr), "l"(gaddr) : "memory");
}
__device__ __forceinline__ void cp_commit() {
    asm volatile("cp.async.commit_group;" ::: "memory");
}
template <int N> __device__ __forceinline__ void cp_wait() {
    asm volatile("cp.async.wait_group %0;" :: "n"(N) : "memory");
}
__device__ __forceinline__ void ldm_x4(uint32_t* r, uint32_t saddr) {
    asm volatile("ldmatrix.sync.aligned.m8n8.x4.shared.b16 {%0,%1,%2,%3}, [%4];"
                 : "=r"(r[0]), "=r"(r[1]), "=r"(r[2]), "=r"(r[3])
                 : "r"(saddr));
}
__device__ __forceinline__ void mma_fp16(float* c, const uint32_t* a,
                                         uint32_t b0, uint32_t b1) {
    asm volatile(
        "mma.sync.aligned.m16n8k16.row.col.f32.f16.f16.f32 "
        "{%0,%1,%2,%3}, {%4,%5,%6,%7}, {%8,%9}, {%0,%1,%2,%3};"
        : "+f"(c[0]), "+f"(c[1]), "+f"(c[2]), "+f"(c[3])
        : "r"(a[0]), "r"(a[1]), "r"(a[2]), "r"(a[3]), "r"(b0), "r"(b1));
}
// Streaming (evict-first) 16B read — for data read exactly once.
__device__ __forceinline__ float4 ld_cs_f4(const float* p) {
    float4 v;
    asm volatile("ld.global.cs.v4.f32 {%0, %1, %2, %3}, [%4];"
                 : "=f"(v.x), "=f"(v.y), "=f"(v.z), "=f"(v.w) : "l"(p));
    return v;
}

// Warp-inclusive scan
__device__ __forceinline__ int warp_iscan(int v, int lane) {
    #pragma unroll
    for (int off = 1; off < 32; off <<= 1) {
        int t = __shfl_up_sync(0xFFFFFFFF, v, off);
        if (lane >= off) v += t;
    }
    return v;
}

__device__ __forceinline__ int block_escan256(int v, int tid, int* smem8, int* total) {
    const int lane = tid & 31, wid = tid >> 5;
    int inc = warp_iscan(v, lane);
    if (lane == 31) smem8[wid] = inc;
    __syncthreads();
    if (wid == 0) {
        int ws = (lane < 8) ? smem8[lane] : 0;
        ws = warp_iscan(ws, lane);
        if (lane < 8) smem8[lane] = ws;
    }
    __syncthreads();
    int woff = (wid > 0) ? smem8[wid - 1] : 0;
    *total = smem8[7];
    return inc - v + woff;
}

// ---------------------------------------------------------------------------
// CSR build
// ---------------------------------------------------------------------------
__global__ void zero_cnt_kernel() {
    int i = blockIdx.x * blockDim.x + threadIdx.x;
    if (i < N_NODES) g_cnt[i] = 0;
}

// hist: 4 edges per thread via int4
__global__ void __launch_bounds__(256) hist_kernel(const int* __restrict__ dst) {
    int t = blockIdx.x * blockDim.x + threadIdx.x;
    if (t * 4 < N_EDGES) {
        int4 d = __ldg((const int4*)dst + t);
        atomicAdd(&g_cnt[d.x], 1);
        atomicAdd(&g_cnt[d.y], 1);
        atomicAdd(&g_cnt[d.z], 1);
        atomicAdd(&g_cnt[d.w], 1);
    }
}

__global__ void __launch_bounds__(256) scan1_kernel() {
    __shared__ int smem8[8];
    int tid = threadIdx.x;
    int i = blockIdx.x * 256 + tid;
    int v = (i < N_NODES) ? g_cnt[i] : 0;
    int total;
    int excl = block_escan256(v, tid, smem8, &total);
    if (i < N_NODES) g_row[i] = excl;
    if (tid == 0) g_bsum[blockIdx.x] = total;
}

__global__ void __launch_bounds__(256) scan2_kernel() {
    __shared__ int smem8[8];
    int tid = threadIdx.x;
    int v = (tid < SCAN_NB) ? g_bsum[tid] : 0;
    int total;
    int excl = block_escan256(v, tid, smem8, &total);
    if (tid < SCAN_NB) g_boff[tid] = excl;
}

__global__ void __launch_bounds__(256) scan3_kernel() {
    int i = blockIdx.x * 256 + threadIdx.x;
    if (i < N_NODES) {
        int r = g_row[i] + g_boff[i >> 8];
        g_row[i]  = r;
        g_work[i] = r;
    }
    if (i == 0) g_row[N_NODES] = N_EDGES;
}

// scatter: 4 edges per thread via int4
__global__ void __launch_bounds__(256) scatter_csr_kernel(
    const int* __restrict__ src, const int* __restrict__ dst)
{
    int t = blockIdx.x * blockDim.x + threadIdx.x;
    if (t * 4 < N_EDGES) {
        int4 s = __ldg((const int4*)src + t);
        int4 d = __ldg((const int4*)dst + t);
        g_csr[atomicAdd(&g_work[d.x], 1)] = s.x;
        g_csr[atomicAdd(&g_work[d.y], 1)] = s.y;
        g_csr[atomicAdd(&g_work[d.z], 1)] = s.z;
        g_csr[atomicAdd(&g_work[d.w], 1)] = s.w;
    }
}

// ---------------------------------------------------------------------------
// Convert x fp32 -> fp16. Streaming reads of x (read-once), normal stores of
// x16 so it stays L2-resident for the gather.
// ---------------------------------------------------------------------------
__global__ void __launch_bounds__(256) convert_x_kernel(const float* __restrict__ x) {
    size_t i = ((size_t)blockIdx.x * blockDim.x + threadIdx.x) * 4;
    if (i >= (size_t)N_NODES * D) return;
    float4 v = ld_cs_f4(x + i);
    __half h[4] = {__float2half_rn(v.x), __float2half_rn(v.y),
                   __float2half_rn(v.z), __float2half_rn(v.w)};
    *(uint2*)(g_x16 + i) = *(uint2*)h;
}

// ---------------------------------------------------------------------------
// Aggregation: one 128-thread block per node; fp16 gathers, fp32 accumulate,
// normal stores (x16 + g_a both fit L2; keep g_a resident for the GEMM).
// ---------------------------------------------------------------------------
__global__ void __launch_bounds__(128) agg_kernel() {
    const int node = blockIdx.x;
    const int tid  = threadIdx.x;

    float4 acc = make_float4(0.f, 0.f, 0.f, 0.f);

    if (node < N_NODES) {
        const int s0 = g_row[node];
        const int s1 = g_row[node + 1];
        int e = s0;
        for (; e + 3 < s1; e += 4) {
            int sa = __ldg(&g_csr[e]);
            int sb = __ldg(&g_csr[e + 1]);
            int sc = __ldg(&g_csr[e + 2]);
            int sd = __ldg(&g_csr[e + 3]);
            __half2 va[2], vb[2], vc[2], vd[2];
            *(uint2*)va = __ldg((const uint2*)(g_x16 + (size_t)sa * D) + tid);
            *(uint2*)vb = __ldg((const uint2*)(g_x16 + (size_t)sb * D) + tid);
            *(uint2*)vc = __ldg((const uint2*)(g_x16 + (size_t)sc * D) + tid);
            *(uint2*)vd = __ldg((const uint2*)(g_x16 + (size_t)sd * D) + tid);
            float2 a0 = __half22float2(va[0]), a1 = __half22float2(va[1]);
            float2 b0 = __half22float2(vb[0]), b1 = __half22float2(vb[1]);
            float2 c0 = __half22float2(vc[0]), c1 = __half22float2(vc[1]);
            float2 d0 = __half22float2(vd[0]), d1 = __half22float2(vd[1]);
            acc.x += a0.x + b0.x + c0.x + d0.x;
            acc.y += a0.y + b0.y + c0.y + d0.y;
            acc.z += a1.x + b1.x + c1.x + d1.x;
            acc.w += a1.y + b1.y + c1.y + d1.y;
        }
        for (; e < s1; e++) {
            int sa = __ldg(&g_csr[e]);
            __half2 va[2];
            *(uint2*)va = __ldg((const uint2*)(g_x16 + (size_t)sa * D) + tid);
            float2 a0 = __half22float2(va[0]), a1 = __half22float2(va[1]);
            acc.x += a0.x; acc.y += a0.y; acc.z += a1.x; acc.w += a1.y;
        }
    }

    __half h[4] = {__float2half_rn(acc.x), __float2half_rn(acc.y),
                   __float2half_rn(acc.z), __float2half_rn(acc.w)};
    *(uint2*)(g_a + (size_t)node * D + tid * 4) = *(uint2*)h;
}

// ---------------------------------------------------------------------------
// Convert + transpose W fp32 [K,N] -> Wt fp16 [N,K]
// ---------------------------------------------------------------------------
__global__ void __launch_bounds__(256) convert_w_kernel(const float* __restrict__ W) {
    int idx = blockIdx.x * blockDim.x + threadIdx.x;
    if (idx >= D * D) return;
    int k = idx >> 9, n = idx & 511;
    g_wt[(size_t)n * D + k] = __float2half_rn(W[idx]);
}

// ---------------------------------------------------------------------------
// mma.sync fp16 single-product GEMM: C = A @ Wt^T + bias
// CTA 128x128, BK=32, 2-stage double buffer, 8 warps, warp tile 64x32.
// ---------------------------------------------------------------------------
#define BK      32
#define KP      40                    // padded smem row stride (elements)
#define TILE_B  (128 * KP * 2)        // 10240 B per tile
#define STAGE_B (2 * TILE_B)          // A, B = 20480 B
#define STAGES  2
#define SMEM_TOTAL (STAGES * STAGE_B) // 40960 B
#define NK      (D / BK)              // 16

__global__ void __launch_bounds__(256, 2) gemm_mma_kernel(
    const float* __restrict__ bias,
    float* __restrict__ C)
{
    extern __shared__ char smem[];
    const uint32_t smem_base = smem_u32(smem);
    const int tid  = threadIdx.x;
    const int wid  = tid >> 5;
    const int lane = tid & 31;
    const int wm   = wid >> 2;
    const int wn   = wid & 3;
    const int block_m = blockIdx.y * 128;
    const int block_n = blockIdx.x * 128;

    auto load_chunk = [&](int kt, int stage) {
        const int k0 = kt * BK;
        const uint32_t sb = smem_base + stage * STAGE_B;
        #pragma unroll
        for (int it = 0; it < 4; it++) {
            const int cid  = it * 256 + tid;      // 0..1023
            const int tile = cid >> 9;            // 0..1
            const int r    = (cid >> 2) & 127;
            const int c4   = cid & 3;
            const __half* g;
            if (tile == 0) g = g_a  + (size_t)(block_m + r) * D;
            else           g = g_wt + (size_t)(block_n + r) * D;
            cp_async16(sb + tile * TILE_B + r * (KP * 2) + c4 * 16,
                       g + k0 + c4 * 8);
        }
        cp_commit();
    };

    float acc[4][4][4];
    #pragma unroll
    for (int i = 0; i < 4; i++)
        #pragma unroll
        for (int j = 0; j < 4; j++)
            #pragma unroll
            for (int e = 0; e < 4; e++)
                acc[i][j][e] = 0.f;

    load_chunk(0, 0);

    const uint32_t row_off = (uint32_t)(lane & 15) * (KP * 2);
    const uint32_t k_lane  = (uint32_t)((lane >> 4) << 4);

    for (int kt = 0; kt < NK; kt++) {
        if (kt + 1 < NK) {
            load_chunk(kt + 1, (kt + 1) & 1);
            cp_wait<1>();
        } else {
            cp_wait<0>();
        }
        __syncthreads();

        const uint32_t sb  = smem_base + (kt & 1) * STAGE_B;
        const uint32_t aF0 = sb + 0 * TILE_B + (wm * 64) * (KP * 2) + row_off;
        const uint32_t bF0 = sb + 1 * TILE_B + (wn * 32) * (KP * 2) + row_off;

        #pragma unroll
        for (int ks = 0; ks < 2; ks++) {
            const uint32_t koff = ks * 32 + k_lane;
            uint32_t bF[2][4];
            #pragma unroll
            for (int np = 0; np < 2; np++)
                ldm_x4(bF[np], bF0 + np * 16 * (KP * 2) + koff);
            #pragma unroll
            for (int mt = 0; mt < 4; mt++) {
                uint32_t aF[4];
                ldm_x4(aF, aF0 + mt * 16 * (KP * 2) + koff);
                #pragma unroll
                for (int nt = 0; nt < 4; nt++) {
                    const int np = nt >> 1, sel = nt & 1;
                    mma_fp16(acc[mt][nt], aF, bF[np][sel], bF[np][sel + 2]);
                }
            }
        }
        __syncthreads();
    }

    #pragma unroll
    for (int nt = 0; nt < 4; nt++) {
        const int col = block_n + wn * 32 + nt * 8 + (lane & 3) * 2;
        const float2 bv = *(const float2*)(bias + col);
        #pragma unroll
        for (int mt = 0; mt < 4; mt++) {
            const int r0 = block_m + wm * 64 + mt * 16 + (lane >> 2);
            const int r1 = r0 + 8;
            if (r0 < N_NODES) {
                float2 o = make_float2(acc[mt][nt][0] + bv.x,
                                       acc[mt][nt][1] + bv.y);
                *(float2*)(C + (size_t)r0 * D + col) = o;
            }
            if (r1 < N_NODES) {
                float2 o = make_float2(acc[mt][nt][2] + bv.x,
                                       acc[mt][nt][3] + bv.y);
                *(float2*)(C + (size_t)r1 * D + col) = o;
            }
        }
    }
}

// ---------------------------------------------------------------------------
extern "C" void kernel_launch(void* const* d_in, const int* in_sizes, int n_in,
                              void* d_out, int out_size)
{
    const float* x      = (const float*)d_in[0];
    const float* weight = (const float*)d_in[1];
    const float* bias   = (const float*)d_in[2];
    const int*   src    = (const int*)d_in[3];
    const int*   dst    = (const int*)d_in[4];
    float*       out    = (float*)d_out;

    // CSR build (parallel scan) + x convert
    zero_cnt_kernel<<<(N_NODES + 255) / 256, 256>>>();
    hist_kernel<<<(N_EDGES / 4 + 255) / 256, 256>>>(dst);
    {
        size_t nthr = (size_t)N_NODES * D / 4;
        convert_x_kernel<<<(unsigned)((nthr + 255) / 256), 256>>>(x);
    }
    scan1_kernel<<<SCAN_NB, 256>>>();
    scan2_kernel<<<1, 256>>>();
    scan3_kernel<<<SCAN_NB, 256>>>();
    scatter_csr_kernel<<<(N_EDGES / 4 + 255) / 256, 256>>>(src, dst);

    // Aggregate from fp16 x -> single fp16 plane (L2-resident)
    agg_kernel<<<M_PAD, 128>>>();

    // Weight convert/transpose (fp16)
    convert_w_kernel<<<(D * D + 255) / 256, 256>>>(weight);

    // GEMM + bias
    {
        static bool attr_set = false;
        if (!attr_set) {
            cudaFuncSetAttribute(gemm_mma_kernel,
                                 cudaFuncAttributeMaxDynamicSharedMemorySize,
                                 SMEM_TOTAL);
            attr_set = true;
        }
        dim3 grid(D / 128, M_PAD / 128);  // (4, 391)
        gemm_mma_kernel<<<grid, 256, SMEM_TOTAL>>>(bias, out);
    }
}

// round 14
// speedup vs baseline: 5.1238x; 1.1041x over previous
#include <cuda_runtime.h>
#include <cuda_fp16.h>
#include <stdint.h>

// GCNConvDGL: out = segment_sum(x[src] -> dst) @ W + bias
// Fused-phase CSR build + fp16 gather-aggregation + single-product fp16 GEMM.

#define N_NODES 50000
#define N_EDGES 800000
#define D       512
#define M_PAD   50048          // 391 * 128
#define SCAN_NB 196            // ceil(50000 / 256)
#define HIST_NB 782            // ceil(200000 / 256)  (int4 edge chunks)
#define CONVX_NB 25000         // 25.6M elems / 4 per thread / 256 threads
#define CONVW_NB 1024          // 512*512/256

// ---------------- scratch (static device globals) ----------------
__device__ __half  g_x16[(size_t)N_NODES * D];  // 51.2 MB
__device__ __half  g_a[(size_t)M_PAD * D];      // 51.2 MB
__device__ __half  g_wt[(size_t)D * D];         // W^T fp16
__device__ int     g_cnt[N_NODES];
__device__ int     g_row[N_NODES + 1];
__device__ int     g_work[N_NODES];
__device__ int     g_csr[N_EDGES];
__device__ int     g_bsum[SCAN_NB];
__device__ int     g_boff[SCAN_NB];

// ---------------- PTX helpers ----------------
__device__ __forceinline__ uint32_t smem_u32(const void* p) {
    uint32_t a;
    asm("{ .reg .u64 t; cvta.to.shared.u64 t, %1; cvt.u32.u64 %0, t; }"
        : "=r"(a) : "l"(p));
    return a;
}
__device__ __forceinline__ void cp_async16(uint32_t saddr, const void* gaddr) {
    asm volatile("cp.async.cg.shared.global [%0], [%1], 16;"
                 :: "r"(saddr), "l"(gaddr) : "memory");
}
__device__ __forceinline__ void cp_commit() {
    asm volatile("cp.async.commit_group;" ::: "memory");
}
template <int N> __device__ __forceinline__ void cp_wait() {
    asm volatile("cp.async.wait_group %0;" :: "n"(N) : "memory");
}
__device__ __forceinline__ void ldm_x4(uint32_t* r, uint32_t saddr) {
    asm volatile("ldmatrix.sync.aligned.m8n8.x4.shared.b16 {%0,%1,%2,%3}, [%4];"
                 : "=r"(r[0]), "=r"(r[1]), "=r"(r[2]), "=r"(r[3])
                 : "r"(saddr));
}
__device__ __forceinline__ void mma_fp16(float* c, const uint32_t* a,
                                         uint32_t b0, uint32_t b1) {
    asm volatile(
        "mma.sync.aligned.m16n8k16.row.col.f32.f16.f16.f32 "
        "{%0,%1,%2,%3}, {%4,%5,%6,%7}, {%8,%9}, {%0,%1,%2,%3};"
        : "+f"(c[0]), "+f"(c[1]), "+f"(c[2]), "+f"(c[3])
        : "r"(a[0]), "r"(a[1]), "r"(a[2]), "r"(a[3]), "r"(b0), "r"(b1));
}
__device__ __forceinline__ float4 ld_cs_f4(const float* p) {
    float4 v;
    asm volatile("ld.global.cs.v4.f32 {%0, %1, %2, %3}, [%4];"
                 : "=f"(v.x), "=f"(v.y), "=f"(v.z), "=f"(v.w) : "l"(p));
    return v;
}

// Warp-inclusive scan
__device__ __forceinline__ int warp_iscan(int v, int lane) {
    #pragma unroll
    for (int off = 1; off < 32; off <<= 1) {
        int t = __shfl_up_sync(0xFFFFFFFF, v, off);
        if (lane >= off) v += t;
    }
    return v;
}

__device__ __forceinline__ int block_escan256(int v, int tid, int* smem8, int* total) {
    const int lane = tid & 31, wid = tid >> 5;
    int inc = warp_iscan(v, lane);
    if (lane == 31) smem8[wid] = inc;
    __syncthreads();
    if (wid == 0) {
        int ws = (lane < 8) ? smem8[lane] : 0;
        ws = warp_iscan(ws, lane);
        if (lane < 8) smem8[lane] = ws;
    }
    __syncthreads();
    int woff = (wid > 0) ? smem8[wid - 1] : 0;
    *total = smem8[7];
    return inc - v + woff;
}

// ---------------------------------------------------------------------------
// zero histogram
// ---------------------------------------------------------------------------
__global__ void zero_cnt_kernel() {
    int i = blockIdx.x * blockDim.x + threadIdx.x;
    if (i < N_NODES) g_cnt[i] = 0;
}

// ---------------------------------------------------------------------------
// FUSED: dst-histogram (blocks [0, HIST_NB)) || x fp32->fp16 convert (rest).
// ---------------------------------------------------------------------------
__global__ void __launch_bounds__(256) fused_hist_convx_kernel(
    const int* __restrict__ dst, const float* __restrict__ x)
{
    if (blockIdx.x < HIST_NB) {
        int t = blockIdx.x * 256 + threadIdx.x;
        if (t < N_EDGES / 4) {
            int4 d = __ldg((const int4*)dst + t);
            atomicAdd(&g_cnt[d.x], 1);
            atomicAdd(&g_cnt[d.y], 1);
            atomicAdd(&g_cnt[d.z], 1);
            atomicAdd(&g_cnt[d.w], 1);
        }
    } else {
        size_t i = ((size_t)(blockIdx.x - HIST_NB) * 256 + threadIdx.x) * 4;
        if (i < (size_t)N_NODES * D) {
            float4 v = ld_cs_f4(x + i);
            __half h[4] = {__float2half_rn(v.x), __float2half_rn(v.y),
                           __float2half_rn(v.z), __float2half_rn(v.w)};
            *(uint2*)(g_x16 + i) = *(uint2*)h;
        }
    }
}

__global__ void __launch_bounds__(256) scan1_kernel() {
    __shared__ int smem8[8];
    int tid = threadIdx.x;
    int i = blockIdx.x * 256 + tid;
    int v = (i < N_NODES) ? g_cnt[i] : 0;
    int total;
    int excl = block_escan256(v, tid, smem8, &total);
    if (i < N_NODES) g_row[i] = excl;
    if (tid == 0) g_bsum[blockIdx.x] = total;
}

__global__ void __launch_bounds__(256) scan2_kernel() {
    __shared__ int smem8[8];
    int tid = threadIdx.x;
    int v = (tid < SCAN_NB) ? g_bsum[tid] : 0;
    int total;
    int excl = block_escan256(v, tid, smem8, &total);
    if (tid < SCAN_NB) g_boff[tid] = excl;
}

__global__ void __launch_bounds__(256) scan3_kernel() {
    int i = blockIdx.x * 256 + threadIdx.x;
    if (i < N_NODES) {
        int r = g_row[i] + g_boff[i >> 8];
        g_row[i]  = r;
        g_work[i] = r;
    }
    if (i == 0) g_row[N_NODES] = N_EDGES;
}

// ---------------------------------------------------------------------------
// FUSED: CSR scatter (blocks [0, HIST_NB)) || W convert/transpose (rest).
// ---------------------------------------------------------------------------
__global__ void __launch_bounds__(256) fused_scatter_convw_kernel(
    const int* __restrict__ src, const int* __restrict__ dst,
    const float* __restrict__ W)
{
    if (blockIdx.x < HIST_NB) {
        int t = blockIdx.x * 256 + threadIdx.x;
        if (t < N_EDGES / 4) {
            int4 s = __ldg((const int4*)src + t);
            int4 d = __ldg((const int4*)dst + t);
            g_csr[atomicAdd(&g_work[d.x], 1)] = s.x;
            g_csr[atomicAdd(&g_work[d.y], 1)] = s.y;
            g_csr[atomicAdd(&g_work[d.z], 1)] = s.z;
            g_csr[atomicAdd(&g_work[d.w], 1)] = s.w;
        }
    } else {
        int idx = (blockIdx.x - HIST_NB) * 256 + threadIdx.x;
        if (idx < D * D) {
            int k = idx >> 9, n = idx & 511;
            g_wt[(size_t)n * D + k] = __float2half_rn(W[idx]);
        }
    }
}

// ---------------------------------------------------------------------------
// Aggregation: one 128-thread block per node; fp16 gathers, fp32 accumulate.
// ---------------------------------------------------------------------------
__global__ void __launch_bounds__(128) agg_kernel() {
    const int node = blockIdx.x;
    const int tid  = threadIdx.x;

    float4 acc = make_float4(0.f, 0.f, 0.f, 0.f);

    if (node < N_NODES) {
        const int s0 = g_row[node];
        const int s1 = g_row[node + 1];
        int e = s0;
        for (; e + 3 < s1; e += 4) {
            int sa = __ldg(&g_csr[e]);
            int sb = __ldg(&g_csr[e + 1]);
            int sc = __ldg(&g_csr[e + 2]);
            int sd = __ldg(&g_csr[e + 3]);
            __half2 va[2], vb[2], vc[2], vd[2];
            *(uint2*)va = __ldg((const uint2*)(g_x16 + (size_t)sa * D) + tid);
            *(uint2*)vb = __ldg((const uint2*)(g_x16 + (size_t)sb * D) + tid);
            *(uint2*)vc = __ldg((const uint2*)(g_x16 + (size_t)sc * D) + tid);
            *(uint2*)vd = __ldg((const uint2*)(g_x16 + (size_t)sd * D) + tid);
            float2 a0 = __half22float2(va[0]), a1 = __half22float2(va[1]);
            float2 b0 = __half22float2(vb[0]), b1 = __half22float2(vb[1]);
            float2 c0 = __half22float2(vc[0]), c1 = __half22float2(vc[1]);
            float2 d0 = __half22float2(vd[0]), d1 = __half22float2(vd[1]);
            acc.x += a0.x + b0.x + c0.x + d0.x;
            acc.y += a0.y + b0.y + c0.y + d0.y;
            acc.z += a1.x + b1.x + c1.x + d1.x;
            acc.w += a1.y + b1.y + c1.y + d1.y;
        }
        for (; e < s1; e++) {
            int sa = __ldg(&g_csr[e]);
            __half2 va[2];
            *(uint2*)va = __ldg((const uint2*)(g_x16 + (size_t)sa * D) + tid);
            float2 a0 = __half22float2(va[0]), a1 = __half22float2(va[1]);
            acc.x += a0.x; acc.y += a0.y; acc.z += a1.x; acc.w += a1.y;
        }
    }

    __half h[4] = {__float2half_rn(acc.x), __float2half_rn(acc.y),
                   __float2half_rn(acc.z), __float2half_rn(acc.w)};
    *(uint2*)(g_a + (size_t)node * D + tid * 4) = *(uint2*)h;
}

// ---------------------------------------------------------------------------
// mma.sync fp16 single-product GEMM: C = A @ Wt^T + bias
// CTA 128x128, BK=32, 3-stage pipeline (depth-2 prefetch, 1 sync/iter),
// 8 warps, warp tile 64x32, 2 CTAs/SM.
// ---------------------------------------------------------------------------
#define BK      32
#define KP      40                    // padded smem row stride (elements)
#define TILE_B  (128 * KP * 2)        // 10240 B per tile
#define STAGE_B (2 * TILE_B)          // A, B = 20480 B
#define STAGES  3
#define SMEM_TOTAL (STAGES * STAGE_B) // 61440 B
#define NK      (D / BK)              // 16

__global__ void __launch_bounds__(256, 2) gemm_mma_kernel(
    const float* __restrict__ bias,
    float* __restrict__ C)
{
    extern __shared__ char smem[];
    const uint32_t smem_base = smem_u32(smem);
    const int tid  = threadIdx.x;
    const int wid  = tid >> 5;
    const int lane = tid & 31;
    const int wm   = wid >> 2;
    const int wn   = wid & 3;
    const int block_m = blockIdx.y * 128;
    const int block_n = blockIdx.x * 128;

    auto load_chunk = [&](int kt, int stage) {
        const int k0 = kt * BK;
        const uint32_t sb = smem_base + stage * STAGE_B;
        #pragma unroll
        for (int it = 0; it < 4; it++) {
            const int cid  = it * 256 + tid;      // 0..1023
            const int tile = cid >> 9;            // 0..1
            const int r    = (cid >> 2) & 127;
            const int c4   = cid & 3;
            const __half* g;
            if (tile == 0) g = g_a  + (size_t)(block_m + r) * D;
            else           g = g_wt + (size_t)(block_n + r) * D;
            cp_async16(sb + tile * TILE_B + r * (KP * 2) + c4 * 16,
                       g + k0 + c4 * 8);
        }
        cp_commit();
    };

    float acc[4][4][4];
    #pragma unroll
    for (int i = 0; i < 4; i++)
        #pragma unroll
        for (int j = 0; j < 4; j++)
            #pragma unroll
            for (int e = 0; e < 4; e++)
                acc[i][j][e] = 0.f;

    load_chunk(0, 0);
    load_chunk(1, 1);

    const uint32_t row_off = (uint32_t)(lane & 15) * (KP * 2);
    const uint32_t k_lane  = (uint32_t)((lane >> 4) << 4);

    for (int kt = 0; kt < NK; kt++) {
        if (kt >= NK - 1) cp_wait<0>(); else cp_wait<1>();
        __syncthreads();
        // Prefetch kt+2 into stage (kt+2)%3 == (kt-1)%3, whose last compute
        // was iteration kt-1 — ordered by the barrier above. One sync/iter.
        if (kt + 2 < NK) load_chunk(kt + 2, (kt + 2) % STAGES);

        const uint32_t sb  = smem_base + (kt % STAGES) * STAGE_B;
        const uint32_t aF0 = sb + 0 * TILE_B + (wm * 64) * (KP * 2) + row_off;
        const uint32_t bF0 = sb + 1 * TILE_B + (wn * 32) * (KP * 2) + row_off;

        #pragma unroll
        for (int ks = 0; ks < 2; ks++) {
            const uint32_t koff = ks * 32 + k_lane;
            uint32_t bF[2][4];
            #pragma unroll
            for (int np = 0; np < 2; np++)
                ldm_x4(bF[np], bF0 + np * 16 * (KP * 2) + koff);
            #pragma unroll
            for (int mt = 0; mt < 4; mt++) {
                uint32_t aF[4];
                ldm_x4(aF, aF0 + mt * 16 * (KP * 2) + koff);
                #pragma unroll
                for (int nt = 0; nt < 4; nt++) {
                    const int np = nt >> 1, sel = nt & 1;
                    mma_fp16(acc[mt][nt], aF, bF[np][sel], bF[np][sel + 2]);
                }
            }
        }
    }

    #pragma unroll
    for (int nt = 0; nt < 4; nt++) {
        const int col = block_n + wn * 32 + nt * 8 + (lane & 3) * 2;
        const float2 bv = *(const float2*)(bias + col);
        #pragma unroll
        for (int mt = 0; mt < 4; mt++) {
            const int r0 = block_m + wm * 64 + mt * 16 + (lane >> 2);
            const int r1 = r0 + 8;
            if (r0 < N_NODES) {
                float2 o = make_float2(acc[mt][nt][0] + bv.x,
                                       acc[mt][nt][1] + bv.y);
                *(float2*)(C + (size_t)r0 * D + col) = o;
            }
            if (r1 < N_NODES) {
                float2 o = make_float2(acc[mt][nt][2] + bv.x,
                                       acc[mt][nt][3] + bv.y);
                *(float2*)(C + (size_t)r1 * D + col) = o;
            }
        }
    }
}

// ---------------------------------------------------------------------------
extern "C" void kernel_launch(void* const* d_in, const int* in_sizes, int n_in,
                              void* d_out, int out_size)
{
    const float* x      = (const float*)d_in[0];
    const float* weight = (const float*)d_in[1];
    const float* bias   = (const float*)d_in[2];
    const int*   src    = (const int*)d_in[3];
    const int*   dst    = (const int*)d_in[4];
    float*       out    = (float*)d_out;

    zero_cnt_kernel<<<(N_NODES + 255) / 256, 256>>>();
    fused_hist_convx_kernel<<<HIST_NB + CONVX_NB, 256>>>(dst, x);
    scan1_kernel<<<SCAN_NB, 256>>>();
    scan2_kernel<<<1, 256>>>();
    scan3_kernel<<<SCAN_NB, 256>>>();
    fused_scatter_convw_kernel<<<HIST_NB + CONVW_NB, 256>>>(src, dst, weight);

    agg_kernel<<<M_PAD, 128>>>();

    {
        static bool attr_set = false;
        if (!attr_set) {
            cudaFuncSetAttribute(gemm_mma_kernel,
                                 cudaFuncAttributeMaxDynamicSharedMemorySize,
                                 SMEM_TOTAL);
            attr_set = true;
        }
        dim3 grid(D / 128, M_PAD / 128);  // (4, 391)
        gemm_mma_kernel<<<grid, 256, SMEM_TOTAL>>>(bias, out);
    }
}